// round 2
// baseline (speedup 1.0000x reference)
#include <cuda_runtime.h>

// Problem constants (fixed shapes from the reference)
#define BATCH 2
#define DIMD  128
#define NCLS  19
#define NP    3600    // 60*60 anchors
#define NN    57600   // 240*240 negatives
#define INV_TEMP 10.0f
#define GAMMA 0.75f
#define EPS 1e-8f

// GEMM tiling
#define BM 128
#define BN 128
#define BK 16
#define TM 8
#define TN 8
#define NTHREADS 256

// Scratch (device globals, no allocation)
__device__ float g_neg_logits[BATCH][NP];
__device__ float g_pos1[BATCH][NP];
__device__ float g_mask1[BATCH][NP];
__device__ int   g_labels1[BATCH][NP];
__device__ int   g_neg_labels[BATCH][NN];

// ---------------------------------------------------------------------------
// Per-anchor prep: labels1 argmax, mask1 (first-true-index quirk), pos1 dot,
// and zero neg_logits accumulator.
// ---------------------------------------------------------------------------
__global__ void prep_anchor_kernel(const float* __restrict__ f1,
                                   const float* __restrict__ f2,
                                   const float* __restrict__ pl1,
                                   const float* __restrict__ pl2) {
    int p = blockIdx.x * blockDim.x + threadIdx.x;
    int b = blockIdx.y;
    if (p >= NP) return;

    const float* pl1b = pl1 + (size_t)b * NCLS * NP;
    const float* pl2b = pl2 + (size_t)b * NCLS * NP;

    // labels1 = argmax_c pl1 (first occurrence of max)
    float best = -1e30f; int bi = 0;
    #pragma unroll
    for (int c = 0; c < NCLS; c++) {
        float v = pl1b[c * NP + p];
        if (v > best) { best = v; bi = c; }
    }
    g_labels1[b][p] = bi;

    // mask1 = argmax_c of ((pl1<pl2)&(pl2>GAMMA)) as float -> index of FIRST
    // true class, 0 if none (matches jnp.argmax on 0/1 vector).
    int mi = -1;
    #pragma unroll
    for (int c = 0; c < NCLS; c++) {
        float a = pl1b[c * NP + p];
        float q = pl2b[c * NP + p];
        if (mi < 0 && (a < q) && (q > GAMMA)) mi = c;
    }
    g_mask1[b][p] = (mi < 0) ? 0.0f : (float)mi;

    // pos1 = dot(f1[:,p], f2[:,p]) / TEMP
    const float* f1b = f1 + (size_t)b * DIMD * NP;
    const float* f2b = f2 + (size_t)b * DIMD * NP;
    float acc = 0.0f;
    #pragma unroll 8
    for (int d = 0; d < DIMD; d++)
        acc += f1b[d * NP + p] * f2b[d * NP + p];
    g_pos1[b][p] = acc * INV_TEMP;

    g_neg_logits[b][p] = 0.0f;
}

// ---------------------------------------------------------------------------
// Per-negative prep: neg_labels argmax
// ---------------------------------------------------------------------------
__global__ void prep_neg_kernel(const float* __restrict__ npl) {
    int n = blockIdx.x * blockDim.x + threadIdx.x;
    int b = blockIdx.y;
    if (n >= NN) return;
    const float* nplb = npl + (size_t)b * NCLS * NN;
    float best = -1e30f; int bi = 0;
    #pragma unroll
    for (int c = 0; c < NCLS; c++) {
        float v = nplb[c * NN + n];
        if (v > best) { best = v; bi = c; }
    }
    g_neg_labels[b][n] = bi;
}

// ---------------------------------------------------------------------------
// Main fused kernel: scores = f1^T(DxP) @ nf(DxN), then per-element
//   if (labels1[p] != neg_labels[n]) sum += exp(score/TEMP)
// row-reduced into g_neg_logits[b][p] via shfl + atomicAdd.
// Both operands are K-major ([D][P] and [D][N]) so smem tile loads are
// contiguous row segments -> fully coalesced, no transpose pass needed.
// ---------------------------------------------------------------------------
__global__ __launch_bounds__(NTHREADS)
void neg_gemm_kernel(const float* __restrict__ f1,
                     const float* __restrict__ nf) {
    const int b  = blockIdx.z;
    const int n0 = blockIdx.x * BN;   // N divisible by 128 -> always full
    const int p0 = blockIdx.y * BM;   // P=3600: last tile partial (16 rows)

    const float* A = f1 + (size_t)b * DIMD * NP;   // [D][P]
    const float* Bm = nf + (size_t)b * DIMD * NN;  // [D][N]

    __shared__ float As[BK][BM];
    __shared__ float Bs[BK][BN];

    const int tid = threadIdx.x;
    const int tx = tid & 15;   // n direction (16 threads)
    const int ty = tid >> 4;   // p direction (16 threads)

    float acc[TM][TN];
    #pragma unroll
    for (int i = 0; i < TM; i++)
        #pragma unroll
        for (int j = 0; j < TN; j++) acc[i][j] = 0.0f;

    // K loop
    for (int k0 = 0; k0 < DIMD; k0 += BK) {
        // Load As: BK*BM = 2048 floats = 512 float4, 2 per thread
        #pragma unroll
        for (int i = 0; i < 2; i++) {
            int q  = tid + i * NTHREADS;       // float4 index
            int kk = q >> 5;                   // row within tile (32 f4/row)
            int pp = (q & 31) << 2;            // col (float index)
            float4 v;
            if (p0 + pp < NP) {
                v = *reinterpret_cast<const float4*>(&A[(size_t)(k0 + kk) * NP + p0 + pp]);
            } else {
                v = make_float4(0.f, 0.f, 0.f, 0.f);
            }
            *reinterpret_cast<float4*>(&As[kk][pp]) = v;
        }
        // Load Bs: always in bounds
        #pragma unroll
        for (int i = 0; i < 2; i++) {
            int q  = tid + i * NTHREADS;
            int kk = q >> 5;
            int nn = (q & 31) << 2;
            float4 v = *reinterpret_cast<const float4*>(&Bm[(size_t)(k0 + kk) * NN + n0 + nn]);
            *reinterpret_cast<float4*>(&Bs[kk][nn]) = v;
        }
        __syncthreads();

        #pragma unroll
        for (int kk = 0; kk < BK; kk++) {
            float af[TM], bf[TN];
            // vector LDS for frags
            float4 a0 = *reinterpret_cast<const float4*>(&As[kk][ty * TM]);
            float4 a1 = *reinterpret_cast<const float4*>(&As[kk][ty * TM + 4]);
            float4 b0 = *reinterpret_cast<const float4*>(&Bs[kk][tx * TN]);
            float4 b1 = *reinterpret_cast<const float4*>(&Bs[kk][tx * TN + 4]);
            af[0]=a0.x; af[1]=a0.y; af[2]=a0.z; af[3]=a0.w;
            af[4]=a1.x; af[5]=a1.y; af[6]=a1.z; af[7]=a1.w;
            bf[0]=b0.x; bf[1]=b0.y; bf[2]=b0.z; bf[3]=b0.w;
            bf[4]=b1.x; bf[5]=b1.y; bf[6]=b1.z; bf[7]=b1.w;
            #pragma unroll
            for (int i = 0; i < TM; i++)
                #pragma unroll
                for (int j = 0; j < TN; j++)
                    acc[i][j] += af[i] * bf[j];
        }
        __syncthreads();
    }

    // Epilogue: exp + label mask + row reduce
    int labn[TN];
    #pragma unroll
    for (int j = 0; j < TN; j++)
        labn[j] = g_neg_labels[b][n0 + tx * TN + j];

    #pragma unroll
    for (int i = 0; i < TM; i++) {
        int p = p0 + ty * TM + i;
        float s = 0.0f;
        if (p < NP) {
            int lp = g_labels1[b][p];
            #pragma unroll
            for (int j = 0; j < TN; j++) {
                if (lp != labn[j])
                    s += __expf(acc[i][j] * INV_TEMP);
            }
        }
        // reduce across the 16 threads (tx) of this row; they are contiguous
        // lanes (0-15 or 16-31) -> width-16 shfl reduction
        #pragma unroll
        for (int off = 8; off > 0; off >>= 1)
            s += __shfl_down_sync(0xffffffffu, s, off, 16);
        if (tx == 0 && p < NP)
            atomicAdd(&g_neg_logits[b][p], s);
    }
}

// ---------------------------------------------------------------------------
// Finalize: per-sample masked mean of lossn, then 0.1 * (l0 + l1)
// ---------------------------------------------------------------------------
__global__ void finalize_kernel(float* __restrict__ out) {
    __shared__ float s_num[256];
    __shared__ float s_den[256];
    const int tid = threadIdx.x;
    float total = 0.0f;

    for (int b = 0; b < BATCH; b++) {
        float num = 0.0f, den = 0.0f;
        for (int p = tid; p < NP; p += 256) {
            float pe  = expf(g_pos1[b][p]);
            float neg = g_neg_logits[b][p];
            float lossn = -logf(pe / (pe + neg + EPS) + EPS);
            float m = g_mask1[b][p];
            num += m * lossn;
            den += m;
        }
        s_num[tid] = num; s_den[tid] = den;
        __syncthreads();
        for (int s = 128; s > 0; s >>= 1) {
            if (tid < s) { s_num[tid] += s_num[tid + s]; s_den[tid] += s_den[tid + s]; }
            __syncthreads();
        }
        if (tid == 0) total += s_num[0] / (s_den[0] + EPS);
        __syncthreads();
    }
    if (tid == 0) out[0] = 0.1f * total;
}

// ---------------------------------------------------------------------------
extern "C" void kernel_launch(void* const* d_in, const int* in_sizes, int n_in,
                              void* d_out, int out_size) {
    const float* feats_view1 = (const float*)d_in[0];  // [2,128,240,240]
    const float* pos_feats1  = (const float*)d_in[1];  // [2,128,60,60]
    const float* pos_feats2  = (const float*)d_in[2];  // [2,128,60,60]
    const float* plog1       = (const float*)d_in[3];  // [2,19,60,60]
    const float* plog2       = (const float*)d_in[4];  // [2,19,60,60]
    const float* neg_plog    = (const float*)d_in[5];  // [2,19,240,240]
    float* out = (float*)d_out;

    {
        dim3 grid((NP + 255) / 256, BATCH);
        prep_anchor_kernel<<<grid, 256>>>(pos_feats1, pos_feats2, plog1, plog2);
    }
    {
        dim3 grid((NN + 255) / 256, BATCH);
        prep_neg_kernel<<<grid, 256>>>(neg_plog);
    }
    {
        dim3 grid(NN / BN, (NP + BM - 1) / BM, BATCH);  // (450, 29, 2)
        neg_gemm_kernel<<<grid, NTHREADS>>>(pos_feats1, feats_view1);
    }
    finalize_kernel<<<1, 256>>>(out);
}

// round 6
// speedup vs baseline: 4.9049x; 4.9049x over previous
#include <cuda_runtime.h>
#include <cuda_bf16.h>
#include <cstdint>

// Problem constants (fixed shapes from the reference)
#define BATCH 2
#define DIMD  128
#define NCLS  19
#define NP    3600    // 60*60 anchors
#define NP_PAD 3712   // 29 tiles of 128
#define NN    57600   // 240*240 negatives
#define INV_TEMP 10.0f
#define GAMMA 0.75f
#define EPS 1e-8f

// GEMM config
#define NTPC 5        // n-tiles (128 wide) per CTA; 450/5 = 90 groups
#define GROUPS_N 90

// Scratch (device globals, no allocation)
__device__ float g_neg_logits[BATCH][NP];
__device__ float g_pos1[BATCH][NP];
__device__ float g_mask1[BATCH][NP];
__device__ int   g_labels1[BATCH][NP];
__device__ int   g_neg_labels[BATCH][NN];
__device__ __nv_bfloat16 g_Abf[BATCH][NP_PAD][DIMD];  // f1^T * 10, bf16
__device__ __nv_bfloat16 g_Bbf[BATCH][NN][DIMD];      // nf^T, bf16

// ---------------------------------------------------------------------------
// Per-anchor prep: labels1 argmax, mask1 (first-true-index quirk), pos1 dot,
// and zero neg_logits accumulator.
// ---------------------------------------------------------------------------
__global__ void prep_anchor_kernel(const float* __restrict__ f1,
                                   const float* __restrict__ f2,
                                   const float* __restrict__ pl1,
                                   const float* __restrict__ pl2) {
    int p = blockIdx.x * blockDim.x + threadIdx.x;
    int b = blockIdx.y;
    if (p >= NP) return;

    const float* pl1b = pl1 + (size_t)b * NCLS * NP;
    const float* pl2b = pl2 + (size_t)b * NCLS * NP;

    float best = -1e30f; int bi = 0;
    #pragma unroll
    for (int c = 0; c < NCLS; c++) {
        float v = pl1b[c * NP + p];
        if (v > best) { best = v; bi = c; }
    }
    g_labels1[b][p] = bi;

    int mi = -1;
    #pragma unroll
    for (int c = 0; c < NCLS; c++) {
        float a = pl1b[c * NP + p];
        float q = pl2b[c * NP + p];
        if (mi < 0 && (a < q) && (q > GAMMA)) mi = c;
    }
    g_mask1[b][p] = (mi < 0) ? 0.0f : (float)mi;

    const float* f1b = f1 + (size_t)b * DIMD * NP;
    const float* f2b = f2 + (size_t)b * DIMD * NP;
    float acc = 0.0f;
    #pragma unroll 8
    for (int d = 0; d < DIMD; d++)
        acc += f1b[d * NP + p] * f2b[d * NP + p];
    g_pos1[b][p] = acc * INV_TEMP;

    g_neg_logits[b][p] = 0.0f;
}

// ---------------------------------------------------------------------------
// Per-negative prep: neg_labels argmax
// ---------------------------------------------------------------------------
__global__ void prep_neg_kernel(const float* __restrict__ npl) {
    int n = blockIdx.x * blockDim.x + threadIdx.x;
    int b = blockIdx.y;
    if (n >= NN) return;
    const float* nplb = npl + (size_t)b * NCLS * NN;
    float best = -1e30f; int bi = 0;
    #pragma unroll
    for (int c = 0; c < NCLS; c++) {
        float v = nplb[c * NN + n];
        if (v > best) { best = v; bi = c; }
    }
    g_neg_labels[b][n] = bi;
}

// ---------------------------------------------------------------------------
// fp32 [D][ncols] -> bf16 [nrows_pad][D] transposed, scaled. Coalesced both
// directions via a 32x32 smem tile. Out-of-range source cols -> 0.
// ---------------------------------------------------------------------------
__global__ void conv_transpose_kernel(const float* __restrict__ src,
                                      __nv_bfloat16* __restrict__ dst,
                                      int ncols, int nrows_pad, float scale) {
    __shared__ float tile[32][33];
    int b = blockIdx.z;
    const float* s = src + (size_t)b * DIMD * ncols;
    __nv_bfloat16* d = dst + (size_t)b * nrows_pad * DIMD;
    int px = blockIdx.x * 32;  // source col == dst row
    int dy = blockIdx.y * 32;  // d dimension
    int tx = threadIdx.x, ty = threadIdx.y;
    #pragma unroll
    for (int i = 0; i < 4; i++) {
        int dd = dy + ty + i * 8;
        int p  = px + tx;
        float v = (p < ncols) ? s[(size_t)dd * ncols + p] : 0.0f;
        tile[ty + i * 8][tx] = v;
    }
    __syncthreads();
    #pragma unroll
    for (int i = 0; i < 4; i++) {
        int p  = px + ty + i * 8;
        int dd = dy + tx;
        if (p < nrows_pad)
            d[(size_t)p * DIMD + dd] = __float2bfloat16(tile[tx][ty + i * 8] * scale);
    }
}

// ---------------------------------------------------------------------------
// Tensor-core GEMM + fused masked-exp row-sum epilogue.
// A = g_Abf [P_pad][128] (prescaled by 10), B = g_Bbf [N][128].
// Block tile 128(M) x 128(N), K=128 fully resident. 8 warps: 4x2, each 32x64.
// Each CTA processes NTPC consecutive N-tiles reusing the A tile; per-row
// masked exp sums accumulate in registers, one atomicAdd per row per warp.
// ---------------------------------------------------------------------------
__device__ __forceinline__ void ldmx4(uint32_t* r, uint32_t saddr) {
    asm volatile("ldmatrix.sync.aligned.m8n8.x4.shared.b16 {%0,%1,%2,%3}, [%4];"
                 : "=r"(r[0]), "=r"(r[1]), "=r"(r[2]), "=r"(r[3]) : "r"(saddr));
}
__device__ __forceinline__ void mma16816(float* c, const uint32_t* a, const uint32_t* b) {
    asm volatile("mma.sync.aligned.m16n8k16.row.col.f32.bf16.bf16.f32 "
                 "{%0,%1,%2,%3}, {%4,%5,%6,%7}, {%8,%9}, {%0,%1,%2,%3};"
                 : "+f"(c[0]), "+f"(c[1]), "+f"(c[2]), "+f"(c[3])
                 : "r"(a[0]), "r"(a[1]), "r"(a[2]), "r"(a[3]), "r"(b[0]), "r"(b[1]));
}
// swizzled element offset in a [r][128] bf16 tile (16B-chunk XOR swizzle)
__device__ __forceinline__ int swz(int r, int k) {
    return r * 128 + ((((k) >> 3) ^ (r & 7)) << 3) + (k & 7);
}

__global__ __launch_bounds__(256, 1)
void neg_gemm_tc_kernel() {
    extern __shared__ __align__(16) __nv_bfloat16 smem[];
    __nv_bfloat16* Asm = smem;                 // 128*128 bf16 = 32KB
    __nv_bfloat16* Bsm = smem + 128 * 128;     // 32KB
    int* nlab = (int*)(smem + 2 * 128 * 128);  // 128 ints

    const int b   = blockIdx.z;
    const int p0  = blockIdx.y * 128;
    const int ng  = blockIdx.x;
    const int tid = threadIdx.x;
    const int lane = tid & 31;
    const int wid  = tid >> 5;
    const int wm = wid & 3;    // m sub-block (32 rows)
    const int wn = wid >> 2;   // n sub-block (64 cols)

    // ---- load A tile (swizzled), once per CTA ----
    const __nv_bfloat16* Ag = &g_Abf[b][p0][0];
    #pragma unroll
    for (int i = 0; i < 8; i++) {
        int q = tid + i * 256;         // 16B-chunk index, 2048 total
        int r = q >> 4;
        int c = q & 15;
        uint4 v = *reinterpret_cast<const uint4*>(Ag + r * 128 + c * 8);
        int sc = c ^ (r & 7);
        *reinterpret_cast<uint4*>(Asm + r * 128 + sc * 8) = v;
    }

    // row labels for this thread's 4 accumulator rows
    int lp[2][2];
    #pragma unroll
    for (int mi = 0; mi < 2; mi++) {
        int base = p0 + wm * 32 + mi * 16 + (lane >> 2);
        lp[mi][0] = (base     < NP) ? g_labels1[b][base]     : -1;
        lp[mi][1] = (base + 8 < NP) ? g_labels1[b][base + 8] : -1;
    }
    float rs[2][2] = {{0.f, 0.f}, {0.f, 0.f}};

    const uint32_t asmb = (uint32_t)__cvta_generic_to_shared(Asm);
    const uint32_t bsmb = (uint32_t)__cvta_generic_to_shared(Bsm);
    const int n_base = ng * (NTPC * 128);

    for (int nt = 0; nt < NTPC; nt++) {
        const int n0 = n_base + nt * 128;
        __syncthreads();   // Bsm readers from previous iter done (also covers A store)
        const __nv_bfloat16* Bg = &g_Bbf[b][n0][0];
        #pragma unroll
        for (int i = 0; i < 8; i++) {
            int q = tid + i * 256;
            int r = q >> 4;
            int c = q & 15;
            uint4 v = *reinterpret_cast<const uint4*>(Bg + r * 128 + c * 8);
            int sc = c ^ (r & 7);
            *reinterpret_cast<uint4*>(Bsm + r * 128 + sc * 8) = v;
        }
        if (tid < 128) nlab[tid] = g_neg_labels[b][n0 + tid];
        __syncthreads();

        float acc[2][8][4];
        #pragma unroll
        for (int mi = 0; mi < 2; mi++)
            #pragma unroll
            for (int ni = 0; ni < 8; ni++)
                #pragma unroll
                for (int x = 0; x < 4; x++) acc[mi][ni][x] = 0.0f;

        #pragma unroll
        for (int kk = 0; kk < 8; kk++) {
            const int k0 = kk * 16;
            uint32_t afr[2][4];
            #pragma unroll
            for (int mi = 0; mi < 2; mi++) {
                int row = wm * 32 + mi * 16 + (lane & 7) + 8 * ((lane >> 3) & 1);
                int k8  = k0 + 8 * (lane >> 4);
                ldmx4(afr[mi], asmb + 2 * swz(row, k8));
            }
            uint32_t bfr[8][2];
            #pragma unroll
            for (int nj = 0; nj < 4; nj++) {
                int nrow = wn * 64 + nj * 16 + (lane & 7) + 8 * (lane >> 4);
                int k8   = k0 + 8 * ((lane >> 3) & 1);
                uint32_t r4[4];
                ldmx4(r4, bsmb + 2 * swz(nrow, k8));
                bfr[nj * 2][0]     = r4[0]; bfr[nj * 2][1]     = r4[1];
                bfr[nj * 2 + 1][0] = r4[2]; bfr[nj * 2 + 1][1] = r4[3];
            }
            #pragma unroll
            for (int mi = 0; mi < 2; mi++)
                #pragma unroll
                for (int ni = 0; ni < 8; ni++)
                    mma16816(acc[mi][ni], afr[mi], bfr[ni]);
        }

        // fused epilogue: exp + label mask, accumulate per-row sums in regs
        #pragma unroll
        for (int ni = 0; ni < 8; ni++) {
            int c0  = wn * 64 + ni * 8 + 2 * (lane & 3);
            int ln0 = nlab[c0];
            int ln1 = nlab[c0 + 1];
            #pragma unroll
            for (int mi = 0; mi < 2; mi++) {
                float e0 = __expf(acc[mi][ni][0]);
                float e1 = __expf(acc[mi][ni][1]);
                float e2 = __expf(acc[mi][ni][2]);
                float e3 = __expf(acc[mi][ni][3]);
                rs[mi][0] += (lp[mi][0] != ln0 ? e0 : 0.f) + (lp[mi][0] != ln1 ? e1 : 0.f);
                rs[mi][1] += (lp[mi][1] != ln0 ? e2 : 0.f) + (lp[mi][1] != ln1 ? e3 : 0.f);
            }
        }
    }

    // width-4 shfl reduce (lanes sharing a row) + atomicAdd
    #pragma unroll
    for (int mi = 0; mi < 2; mi++)
        #pragma unroll
        for (int h = 0; h < 2; h++) {
            float s = rs[mi][h];
            s += __shfl_xor_sync(0xffffffffu, s, 1);
            s += __shfl_xor_sync(0xffffffffu, s, 2);
            int p = p0 + wm * 32 + mi * 16 + (lane >> 2) + h * 8;
            if ((lane & 3) == 0 && p < NP)
                atomicAdd(&g_neg_logits[b][p], s);
        }
}

// ---------------------------------------------------------------------------
// Finalize: per-sample masked mean of lossn, then 0.1 * (l0 + l1)
// ---------------------------------------------------------------------------
__global__ void finalize_kernel(float* __restrict__ out) {
    __shared__ float s_num[1024];
    __shared__ float s_den[1024];
    const int tid = threadIdx.x;
    float total = 0.0f;

    for (int b = 0; b < BATCH; b++) {
        float num = 0.0f, den = 0.0f;
        for (int p = tid; p < NP; p += 1024) {
            float pe  = expf(g_pos1[b][p]);
            float neg = g_neg_logits[b][p];
            float lossn = -logf(pe / (pe + neg + EPS) + EPS);
            float m = g_mask1[b][p];
            num += m * lossn;
            den += m;
        }
        s_num[tid] = num; s_den[tid] = den;
        __syncthreads();
        for (int s = 512; s > 0; s >>= 1) {
            if (tid < s) { s_num[tid] += s_num[tid + s]; s_den[tid] += s_den[tid + s]; }
            __syncthreads();
        }
        if (tid == 0) total += s_num[0] / (s_den[0] + EPS);
        __syncthreads();
    }
    if (tid == 0) out[0] = 0.1f * total;
}

// ---------------------------------------------------------------------------
extern "C" void kernel_launch(void* const* d_in, const int* in_sizes, int n_in,
                              void* d_out, int out_size) {
    const float* feats_view1 = (const float*)d_in[0];  // [2,128,240,240]
    const float* pos_feats1  = (const float*)d_in[1];  // [2,128,60,60]
    const float* pos_feats2  = (const float*)d_in[2];  // [2,128,60,60]
    const float* plog1       = (const float*)d_in[3];  // [2,19,60,60]
    const float* plog2       = (const float*)d_in[4];  // [2,19,60,60]
    const float* neg_plog    = (const float*)d_in[5];  // [2,19,240,240]
    float* out = (float*)d_out;

    static __nv_bfloat16* pA = nullptr;
    static __nv_bfloat16* pB = nullptr;
    // resolve device-global addresses (host side; cheap, deterministic)
    if (!pA) { cudaGetSymbolAddress((void**)&pA, g_Abf); }
    if (!pB) { cudaGetSymbolAddress((void**)&pB, g_Bbf); }

    const int smem_bytes = 2 * 128 * 128 * 2 + 128 * 4;  // 66048
    static bool attr_set = false;
    if (!attr_set) {
        cudaFuncSetAttribute(neg_gemm_tc_kernel,
                             cudaFuncAttributeMaxDynamicSharedMemorySize, smem_bytes);
        attr_set = true;
    }

    {
        dim3 grid((NP + 255) / 256, BATCH);
        prep_anchor_kernel<<<grid, 256>>>(pos_feats1, pos_feats2, plog1, plog2);
    }
    {
        dim3 grid((NN + 255) / 256, BATCH);
        prep_neg_kernel<<<grid, 256>>>(neg_plog);
    }
    {   // A: f1 [D][P] -> [P_pad][D] bf16, prescaled by 1/TEMP
        dim3 grid(NP_PAD / 32, DIMD / 32, BATCH);
        conv_transpose_kernel<<<grid, dim3(32, 8)>>>(pos_feats1, pA, NP, NP_PAD, INV_TEMP);
    }
    {   // B: nf [D][N] -> [N][D] bf16
        dim3 grid(NN / 32, DIMD / 32, BATCH);
        conv_transpose_kernel<<<grid, dim3(32, 8)>>>(feats_view1, pB, NN, NN, 1.0f);
    }
    {
        dim3 grid(GROUPS_N, NP_PAD / 128, BATCH);   // (90, 29, 2)
        neg_gemm_tc_kernel<<<grid, 256, smem_bytes>>>();
    }
    finalize_kernel<<<1, 1024>>>(out);
}

// round 8
// speedup vs baseline: 6.3593x; 1.2965x over previous
#include <cuda_runtime.h>
#include <cuda_bf16.h>
#include <cstdint>

// Problem constants (fixed shapes from the reference)
#define BATCH 2
#define DIMD  128
#define NCLS  19
#define NP    3600    // 60*60 anchors
#define NP_PAD 3712   // 29 tiles of 128
#define NN    57600   // 240*240 negatives
#define INV_TEMP 10.0f
#define GAMMA 0.75f
#define EPS 1e-8f

// GEMM config: each CTA owns one 128-row A tile and streams NTPC N-tiles of 128
#define NTPC 10
#define GROUPS_N 45   // 45*10*128 = 57600

// idesc: kind::f16, dtype F32, a/b BF16, N=128 (16<<17), M=128 (8<<24)
#define MMA_IDESC 0x08200490u

// Does this device-compilation pass have the sm_103a arch-specific features?
#if defined(__CUDA_ARCH__) && \
    (defined(__CUDA_ARCH_FEAT_SM103_ALL) || \
     (defined(__CUDA_ARCH_SPECIFIC__) && (__CUDA_ARCH_SPECIFIC__ == 1030)) || \
     (defined(__CUDA_ARCH_FAMILY_SPECIFIC__) && (__CUDA_ARCH_FAMILY_SPECIFIC__ == 1030)))
#define HAVE_TC5 1
#else
#define HAVE_TC5 0
#endif

// Scratch (device globals, no allocation)
__device__ float g_neg_logits[BATCH][NP];
__device__ float g_pos1[BATCH][NP];
__device__ float g_mask1[BATCH][NP];
__device__ int   g_labels1[BATCH][NP];
__device__ int   g_neg_labels[BATCH][NN];
__device__ __nv_bfloat16 g_Abf[BATCH][NP_PAD][DIMD];  // f1^T * 10, bf16
__device__ __nv_bfloat16 g_Bbf[BATCH][NN][DIMD];      // nf^T, bf16

// ---------------------------------------------------------------------------
// Per-anchor prep
// ---------------------------------------------------------------------------
__global__ void prep_anchor_kernel(const float* __restrict__ f1,
                                   const float* __restrict__ f2,
                                   const float* __restrict__ pl1,
                                   const float* __restrict__ pl2) {
    int p = blockIdx.x * blockDim.x + threadIdx.x;
    int b = blockIdx.y;
    if (p >= NP) return;

    const float* pl1b = pl1 + (size_t)b * NCLS * NP;
    const float* pl2b = pl2 + (size_t)b * NCLS * NP;

    float best = -1e30f; int bi = 0;
    #pragma unroll
    for (int c = 0; c < NCLS; c++) {
        float v = pl1b[c * NP + p];
        if (v > best) { best = v; bi = c; }
    }
    g_labels1[b][p] = bi;

    int mi = -1;
    #pragma unroll
    for (int c = 0; c < NCLS; c++) {
        float a = pl1b[c * NP + p];
        float q = pl2b[c * NP + p];
        if (mi < 0 && (a < q) && (q > GAMMA)) mi = c;
    }
    g_mask1[b][p] = (mi < 0) ? 0.0f : (float)mi;

    const float* f1b = f1 + (size_t)b * DIMD * NP;
    const float* f2b = f2 + (size_t)b * DIMD * NP;
    float acc = 0.0f;
    #pragma unroll 8
    for (int d = 0; d < DIMD; d++)
        acc += f1b[d * NP + p] * f2b[d * NP + p];
    g_pos1[b][p] = acc * INV_TEMP;

    g_neg_logits[b][p] = 0.0f;
}

// ---------------------------------------------------------------------------
// Per-negative prep
// ---------------------------------------------------------------------------
__global__ void prep_neg_kernel(const float* __restrict__ npl) {
    int n = blockIdx.x * blockDim.x + threadIdx.x;
    int b = blockIdx.y;
    if (n >= NN) return;
    const float* nplb = npl + (size_t)b * NCLS * NN;
    float best = -1e30f; int bi = 0;
    #pragma unroll
    for (int c = 0; c < NCLS; c++) {
        float v = nplb[c * NN + n];
        if (v > best) { best = v; bi = c; }
    }
    g_neg_labels[b][n] = bi;
}

// ---------------------------------------------------------------------------
// fp32 [D][ncols] -> bf16 [nrows_pad][D] transposed, scaled.
// ---------------------------------------------------------------------------
__global__ void conv_transpose_kernel(const float* __restrict__ src,
                                      __nv_bfloat16* __restrict__ dst,
                                      int ncols, int nrows_pad, float scale) {
    __shared__ float tile[32][33];
    int b = blockIdx.z;
    const float* s = src + (size_t)b * DIMD * ncols;
    __nv_bfloat16* d = dst + (size_t)b * nrows_pad * DIMD;
    int px = blockIdx.x * 32;
    int dy = blockIdx.y * 32;
    int tx = threadIdx.x, ty = threadIdx.y;
    #pragma unroll
    for (int i = 0; i < 4; i++) {
        int dd = dy + ty + i * 8;
        int p  = px + tx;
        float v = (p < ncols) ? s[(size_t)dd * ncols + p] : 0.0f;
        tile[ty + i * 8][tx] = v;
    }
    __syncthreads();
    #pragma unroll
    for (int i = 0; i < 4; i++) {
        int p  = px + ty + i * 8;
        int dd = dy + tx;
        if (p < nrows_pad)
            d[(size_t)p * DIMD + dd] = __float2bfloat16(tile[tx][ty + i * 8] * scale);
    }
}

// ---------------------------------------------------------------------------
// Shared helpers
// ---------------------------------------------------------------------------
// Load a [128 rows x 128 bf16] tile from row-major global into K-blocked
// SW128 SMEM: two blocks of [128 rows x 64 bf16] (128B rows, XOR swizzle).
__device__ __forceinline__ void load_tile128(const __nv_bfloat16* __restrict__ g,
                                             uint8_t* __restrict__ s, int tid) {
    #pragma unroll
    for (int i = 0; i < 8; i++) {
        int q = tid + i * 256;         // 16B-chunk index, 2048 total
        int r = q >> 4;                // row 0..127
        int c = q & 15;                // chunk 0..15
        uint4 v = *reinterpret_cast<const uint4*>(g + (size_t)r * 128 + c * 8);
        int blk = c >> 3;
        int cc  = (c & 7) ^ (r & 7);
        *reinterpret_cast<uint4*>(s + blk * 16384 + r * 128 + cc * 16) = v;
    }
}

// SMEM layout offsets (bytes, from 1024-aligned base) -- tcgen05 path
#define OFF_A     0u
#define OFF_B     32768u      // two buffers of 32KB
#define OFF_NLAB  98304u      // 2 x 128 ints
#define OFF_TPTR  99328u
#define OFF_MBAR  99344u      // 2 x 8B
#define SMEM_REQ  (99360 + 1024)

#if HAVE_TC5
// ---------------------------------------------------------------------------
// tcgen05 helpers (sm_103a-only pass)
// ---------------------------------------------------------------------------
static constexpr uint64_t SMEM_DESC_BASE_SW128 =
    (uint64_t(2)  << 61) | (uint64_t(1) << 46) | (uint64_t(64) << 32) | (uint64_t(1) << 16);

__device__ __forceinline__ uint64_t make_desc(uint32_t saddr) {
    return SMEM_DESC_BASE_SW128 | ((uint64_t)(saddr >> 4) & 0x3FFF);
}

__device__ __forceinline__ bool elect1() {
    uint32_t p;
    asm volatile("{\n\t.reg .pred p;\n\telect.sync _|p, 0xFFFFFFFF;\n\tselp.b32 %0, 1, 0, p;\n\t}"
                 : "=r"(p));
    return p != 0;
}

__device__ __forceinline__ void mma_bf16_ss(uint32_t d, uint64_t a, uint64_t b,
                                            uint32_t en) {
    asm volatile(
        "{\n\t.reg .pred p;\n\tsetp.ne.u32 p, %4, 0;\n\t"
        "tcgen05.mma.cta_group::1.kind::f16 [%0], %1, %2, %3, {%5,%5,%5,%5}, p;\n\t}"
        :: "r"(d), "l"(a), "l"(b), "r"(MMA_IDESC), "r"(en), "r"(0u)
        : "memory");
}

__device__ __forceinline__ void mbar_init(uint32_t a, uint32_t cnt) {
    asm volatile("mbarrier.init.shared.b64 [%0], %1;" :: "r"(a), "r"(cnt) : "memory");
}
__device__ __forceinline__ void mbar_wait(uint32_t a, uint32_t ph) {
    asm volatile(
        "{\n\t.reg .pred P1;\n\t"
        "W0_%=:\n\t"
        "mbarrier.try_wait.parity.acquire.cta.shared::cta.b64 P1, [%0], %1, 0x989680;\n\t"
        "@P1 bra W1_%=;\n\t"
        "bra W0_%=;\n\t"
        "W1_%=:\n\t}"
        :: "r"(a), "r"(ph) : "memory");
}

#define TC_ALLOC(sa, n)  asm volatile("tcgen05.alloc.cta_group::1.sync.aligned.shared::cta.b32 [%0], %1;" :: "r"(sa), "r"(n) : "memory")
#define TC_RELINQ()      asm volatile("tcgen05.relinquish_alloc_permit.cta_group::1.sync.aligned;")
#define TC_DEALLOC(t, n) asm volatile("tcgen05.dealloc.cta_group::1.sync.aligned.b32 %0, %1;" :: "r"(t), "r"(n))
#define TC_COMMIT(mb)    asm volatile("tcgen05.commit.cta_group::1.mbarrier::arrive::one.shared::cluster.b64 [%0];" :: "r"(mb) : "memory")
#define TC_WAIT_LD()     asm volatile("tcgen05.wait::ld.sync.aligned;" ::: "memory")
#define TC_FENCE_AFTER() asm volatile("tcgen05.fence::after_thread_sync;" ::: "memory")
#define TC_FENCE_BEFORE() asm volatile("tcgen05.fence::before_thread_sync;" ::: "memory")
#define PROXY_FENCE()    asm volatile("fence.proxy.async.shared::cta;" ::: "memory")

#define LDTM_X32(r, a) \
    asm volatile("tcgen05.ld.sync.aligned.32x32b.x32.b32 " \
        "{%0, %1, %2, %3, %4, %5, %6, %7, " \
        " %8, %9, %10, %11, %12, %13, %14, %15, " \
        " %16, %17, %18, %19, %20, %21, %22, %23, " \
        " %24, %25, %26, %27, %28, %29, %30, %31}, [%32];" \
        : "=r"((r)[0]),  "=r"((r)[1]),  "=r"((r)[2]),  "=r"((r)[3]), \
          "=r"((r)[4]),  "=r"((r)[5]),  "=r"((r)[6]),  "=r"((r)[7]), \
          "=r"((r)[8]),  "=r"((r)[9]),  "=r"((r)[10]), "=r"((r)[11]), \
          "=r"((r)[12]), "=r"((r)[13]), "=r"((r)[14]), "=r"((r)[15]), \
          "=r"((r)[16]), "=r"((r)[17]), "=r"((r)[18]), "=r"((r)[19]), \
          "=r"((r)[20]), "=r"((r)[21]), "=r"((r)[22]), "=r"((r)[23]), \
          "=r"((r)[24]), "=r"((r)[25]), "=r"((r)[26]), "=r"((r)[27]), \
          "=r"((r)[28]), "=r"((r)[29]), "=r"((r)[30]), "=r"((r)[31]) \
        : "r"(a))
#endif  // HAVE_TC5

#if !HAVE_TC5
// ---------------------------------------------------------------------------
// Fallback helpers: mma.sync m16n8k16 bf16 (compiles on any >= sm_80 target)
// ---------------------------------------------------------------------------
__device__ __forceinline__ void ldmx4(uint32_t* r, uint32_t saddr) {
    asm volatile("ldmatrix.sync.aligned.m8n8.x4.shared.b16 {%0,%1,%2,%3}, [%4];"
                 : "=r"(r[0]), "=r"(r[1]), "=r"(r[2]), "=r"(r[3]) : "r"(saddr));
}
__device__ __forceinline__ void mma16816(float* c, const uint32_t* a, const uint32_t* b) {
    asm volatile("mma.sync.aligned.m16n8k16.row.col.f32.bf16.bf16.f32 "
                 "{%0,%1,%2,%3}, {%4,%5,%6,%7}, {%8,%9}, {%0,%1,%2,%3};"
                 : "+f"(c[0]), "+f"(c[1]), "+f"(c[2]), "+f"(c[3])
                 : "r"(a[0]), "r"(a[1]), "r"(a[2]), "r"(a[3]), "r"(b[0]), "r"(b[1]));
}
// swizzled element offset in a flat [r][128] bf16 tile (16B-chunk XOR swizzle)
__device__ __forceinline__ int swz(int r, int k) {
    return r * 128 + ((((k) >> 3) ^ (r & 7)) << 3) + (k & 7);
}
#endif  // !HAVE_TC5

// ---------------------------------------------------------------------------
// GEMM + fused masked-exp row-sum epilogue. One kernel name, two bodies:
// tcgen05 (sm_103a cubin) or mma.sync (virtual-arch / JIT fallback).
// Grid: (GROUPS_N, NP_PAD/128, BATCH), 256 threads, SMEM_REQ dynamic smem.
// ---------------------------------------------------------------------------
__global__ __launch_bounds__(256)
void neg_gemm_kernel() {
    extern __shared__ __align__(16) uint8_t dynsmem[];
    uint8_t* smem = (uint8_t*)(((uintptr_t)dynsmem + 1023) & ~(uintptr_t)1023);

    const int b      = blockIdx.z;
    const int p0     = blockIdx.y * 128;
    const int n_base = blockIdx.x * (NTPC * 128);
    const int tid    = threadIdx.x;
    const int wid    = tid >> 5;
    const int lane   = tid & 31;

#if HAVE_TC5
    // ======================= tcgen05 path =======================
    const uint32_t sb    = (uint32_t)__cvta_generic_to_shared(smem);
    const uint32_t mbar0 = sb + OFF_MBAR;
    const uint32_t mbar1 = sb + OFF_MBAR + 8;

    if (wid == 0) {
        TC_ALLOC(sb + OFF_TPTR, 256u);
        TC_RELINQ();
    }
    if (tid == 0) { mbar_init(mbar0, 1); mbar_init(mbar1, 1); }

    load_tile128(&g_Abf[b][p0][0], smem + OFF_A, tid);
    load_tile128(&g_Bbf[b][n_base][0], smem + OFF_B, tid);
    if (tid < 128) ((int*)(smem + OFF_NLAB))[tid] = g_neg_labels[b][n_base + tid];
    PROXY_FENCE();
    __syncthreads();

    const uint32_t tmem_base = *reinterpret_cast<uint32_t*>(smem + OFF_TPTR);
    const uint64_t adesc = make_desc(sb + OFF_A);

    // issue tile 0
    if (wid == 0) {
        TC_FENCE_AFTER();
        if (elect1()) {
            uint64_t bdesc = make_desc(sb + OFF_B);
            #pragma unroll
            for (int kk = 0; kk < 8; kk++) {
                uint64_t koff = (uint64_t)((kk >> 2) * 1024 + (kk & 3) * 2);
                mma_bf16_ss(tmem_base, adesc + koff, bdesc + koff, kk > 0);
            }
            TC_COMMIT(mbar0);
        }
    }

    const int myrow = (wid & 3) * 32 + lane;
    const int myp   = p0 + myrow;
    const int lp    = (myp < NP) ? g_labels1[b][myp] : -1;
    float rs0 = 0.0f, rs1 = 0.0f;
    const int cbase = (wid >> 2) * 64;  // warpgroup column split

    for (int nt = 1; nt <= NTPC; nt++) {
        const int prev = nt - 1;
        const uint32_t mb_prev = (prev & 1) ? mbar1 : mbar0;

        __syncthreads();                       // epilogue nt-2 fully done
        mbar_wait(mb_prev, (prev >> 1) & 1);   // MMA prev done (=> nt-2 done too)

        if (nt < NTPC) {
            load_tile128(&g_Bbf[b][n_base + nt * 128][0],
                         smem + OFF_B + (nt & 1) * 32768u, tid);
            if (tid < 128)
                ((int*)(smem + OFF_NLAB + (nt & 1) * 512u))[tid] =
                    g_neg_labels[b][n_base + nt * 128 + tid];
            PROXY_FENCE();
        }
        __syncthreads();

        if (nt < NTPC && wid == 0) {
            TC_FENCE_AFTER();
            if (elect1()) {
                uint64_t bdesc = make_desc(sb + OFF_B + (nt & 1) * 32768u);
                uint32_t dtm = tmem_base + (nt & 1) * 128;
                #pragma unroll
                for (int kk = 0; kk < 8; kk++) {
                    uint64_t koff = (uint64_t)((kk >> 2) * 1024 + (kk & 3) * 2);
                    mma_bf16_ss(dtm, adesc + koff, bdesc + koff, kk > 0);
                }
                TC_COMMIT((nt & 1) ? mbar1 : mbar0);
            }
        }

        // ---- epilogue tile prev (overlaps MMA nt) ----
        TC_FENCE_AFTER();
        const int* nl = (const int*)(smem + OFF_NLAB + (prev & 1) * 512u);
        const uint32_t dtm_prev = tmem_base + (prev & 1) * 128;
        #pragma unroll
        for (int ch = 0; ch < 2; ch++) {
            const int c0 = cbase + ch * 32;
            uint32_t r[32];
            LDTM_X32(r, dtm_prev + c0);
            TC_WAIT_LD();
            #pragma unroll
            for (int j = 0; j < 32; j += 2) {
                float e0 = __expf(__uint_as_float(r[j]));
                float e1 = __expf(__uint_as_float(r[j + 1]));
                rs0 += (lp != nl[c0 + j])     ? e0 : 0.0f;
                rs1 += (lp != nl[c0 + j + 1]) ? e1 : 0.0f;
            }
        }
        TC_FENCE_BEFORE();
    }

    if (myp < NP)
        atomicAdd(&g_neg_logits[b][myp], rs0 + rs1);

    __syncthreads();
    if (wid == 0) TC_DEALLOC(tmem_base, 256u);

#else
    // ======================= mma.sync fallback path =======================
    __nv_bfloat16* Asm = (__nv_bfloat16*)smem;             // 32KB (flat [128][128] swz)
    __nv_bfloat16* Bsm = (__nv_bfloat16*)(smem + 32768u);  // 32KB
    int* nlab = (int*)(smem + 65536u);                     // 128 ints

    const int wm = wid & 3;    // m sub-block (32 rows)
    const int wn = wid >> 2;   // n sub-block (64 cols)

    // flat-swizzle A tile load ([r][128], chunk c XOR (r&7))
    const __nv_bfloat16* Ag = &g_Abf[b][p0][0];
    #pragma unroll
    for (int i = 0; i < 8; i++) {
        int q = tid + i * 256;
        int r = q >> 4;
        int c = q & 15;
        uint4 v = *reinterpret_cast<const uint4*>(Ag + (size_t)r * 128 + c * 8);
        int sc = c ^ (r & 7);
        *reinterpret_cast<uint4*>(Asm + r * 128 + sc * 8) = v;
    }

    int lp2[2][2];
    #pragma unroll
    for (int mi = 0; mi < 2; mi++) {
        int base = p0 + wm * 32 + mi * 16 + (lane >> 2);
        lp2[mi][0] = (base     < NP) ? g_labels1[b][base]     : -1;
        lp2[mi][1] = (base + 8 < NP) ? g_labels1[b][base + 8] : -1;
    }
    float rs[2][2] = {{0.f, 0.f}, {0.f, 0.f}};

    const uint32_t asmb = (uint32_t)__cvta_generic_to_shared(Asm);
    const uint32_t bsmb = (uint32_t)__cvta_generic_to_shared(Bsm);

    for (int nt = 0; nt < NTPC; nt++) {
        const int n0 = n_base + nt * 128;
        __syncthreads();
        const __nv_bfloat16* Bg = &g_Bbf[b][n0][0];
        #pragma unroll
        for (int i = 0; i < 8; i++) {
            int q = tid + i * 256;
            int r = q >> 4;
            int c = q & 15;
            uint4 v = *reinterpret_cast<const uint4*>(Bg + (size_t)r * 128 + c * 8);
            int sc = c ^ (r & 7);
            *reinterpret_cast<uint4*>(Bsm + r * 128 + sc * 8) = v;
        }
        if (tid < 128) nlab[tid] = g_neg_labels[b][n0 + tid];
        __syncthreads();

        float acc[2][8][4];
        #pragma unroll
        for (int mi = 0; mi < 2; mi++)
            #pragma unroll
            for (int ni = 0; ni < 8; ni++)
                #pragma unroll
                for (int x = 0; x < 4; x++) acc[mi][ni][x] = 0.0f;

        #pragma unroll
        for (int kk = 0; kk < 8; kk++) {
            const int k0 = kk * 16;
            uint32_t afr[2][4];
            #pragma unroll
            for (int mi = 0; mi < 2; mi++) {
                int row = wm * 32 + mi * 16 + (lane & 7) + 8 * ((lane >> 3) & 1);
                int k8  = k0 + 8 * (lane >> 4);
                ldmx4(afr[mi], asmb + 2 * swz(row, k8));
            }
            uint32_t bfr[8][2];
            #pragma unroll
            for (int nj = 0; nj < 4; nj++) {
                int nrow = wn * 64 + nj * 16 + (lane & 7) + 8 * (lane >> 4);
                int k8   = k0 + 8 * ((lane >> 3) & 1);
                uint32_t r4[4];
                ldmx4(r4, bsmb + 2 * swz(nrow, k8));
                bfr[nj * 2][0]     = r4[0]; bfr[nj * 2][1]     = r4[1];
                bfr[nj * 2 + 1][0] = r4[2]; bfr[nj * 2 + 1][1] = r4[3];
            }
            #pragma unroll
            for (int mi = 0; mi < 2; mi++)
                #pragma unroll
                for (int ni = 0; ni < 8; ni++)
                    mma16816(acc[mi][ni], afr[mi], bfr[ni]);
        }

        #pragma unroll
        for (int ni = 0; ni < 8; ni++) {
            int c0  = wn * 64 + ni * 8 + 2 * (lane & 3);
            int ln0 = nlab[c0];
            int ln1 = nlab[c0 + 1];
            #pragma unroll
            for (int mi = 0; mi < 2; mi++) {
                float e0 = __expf(acc[mi][ni][0]);
                float e1 = __expf(acc[mi][ni][1]);
                float e2 = __expf(acc[mi][ni][2]);
                float e3 = __expf(acc[mi][ni][3]);
                rs[mi][0] += (lp2[mi][0] != ln0 ? e0 : 0.f) + (lp2[mi][0] != ln1 ? e1 : 0.f);
                rs[mi][1] += (lp2[mi][1] != ln0 ? e2 : 0.f) + (lp2[mi][1] != ln1 ? e3 : 0.f);
            }
        }
    }

    #pragma unroll
    for (int mi = 0; mi < 2; mi++)
        #pragma unroll
        for (int h = 0; h < 2; h++) {
            float s = rs[mi][h];
            s += __shfl_xor_sync(0xffffffffu, s, 1);
            s += __shfl_xor_sync(0xffffffffu, s, 2);
            int p = p0 + wm * 32 + mi * 16 + (lane >> 2) + h * 8;
            if ((lane & 3) == 0 && p < NP)
                atomicAdd(&g_neg_logits[b][p], s);
        }
#endif
}

// ---------------------------------------------------------------------------
// Finalize
// ---------------------------------------------------------------------------
__global__ void finalize_kernel(float* __restrict__ out) {
    __shared__ float s_num[1024];
    __shared__ float s_den[1024];
    const int tid = threadIdx.x;
    float total = 0.0f;

    for (int b = 0; b < BATCH; b++) {
        float num = 0.0f, den = 0.0f;
        for (int p = tid; p < NP; p += 1024) {
            float pe  = expf(g_pos1[b][p]);
            float neg = g_neg_logits[b][p];
            float lossn = -logf(pe / (pe + neg + EPS) + EPS);
            float m = g_mask1[b][p];
            num += m * lossn;
            den += m;
        }
        s_num[tid] = num; s_den[tid] = den;
        __syncthreads();
        for (int s = 512; s > 0; s >>= 1) {
            if (tid < s) { s_num[tid] += s_num[tid + s]; s_den[tid] += s_den[tid + s]; }
            __syncthreads();
        }
        if (tid == 0) total += s_num[0] / (s_den[0] + EPS);
        __syncthreads();
    }
    if (tid == 0) out[0] = 0.1f * total;
}

// ---------------------------------------------------------------------------
extern "C" void kernel_launch(void* const* d_in, const int* in_sizes, int n_in,
                              void* d_out, int out_size) {
    const float* feats_view1 = (const float*)d_in[0];  // [2,128,240,240]
    const float* pos_feats1  = (const float*)d_in[1];  // [2,128,60,60]
    const float* pos_feats2  = (const float*)d_in[2];  // [2,128,60,60]
    const float* plog1       = (const float*)d_in[3];  // [2,19,60,60]
    const float* plog2       = (const float*)d_in[4];  // [2,19,60,60]
    const float* neg_plog    = (const float*)d_in[5];  // [2,19,240,240]
    float* out = (float*)d_out;

    static __nv_bfloat16* pA = nullptr;
    static __nv_bfloat16* pB = nullptr;
    if (!pA) { cudaGetSymbolAddress((void**)&pA, g_Abf); }
    if (!pB) { cudaGetSymbolAddress((void**)&pB, g_Bbf); }

    static bool attr_set = false;
    if (!attr_set) {
        cudaFuncSetAttribute(neg_gemm_kernel,
                             cudaFuncAttributeMaxDynamicSharedMemorySize, SMEM_REQ);
        attr_set = true;
    }

    {
        dim3 grid((NP + 255) / 256, BATCH);
        prep_anchor_kernel<<<grid, 256>>>(pos_feats1, pos_feats2, plog1, plog2);
    }
    {
        dim3 grid((NN + 255) / 256, BATCH);
        prep_neg_kernel<<<grid, 256>>>(neg_plog);
    }
    {   // A: f1 [D][P] -> [P_pad][D] bf16, prescaled by 1/TEMP
        dim3 grid(NP_PAD / 32, DIMD / 32, BATCH);
        conv_transpose_kernel<<<grid, dim3(32, 8)>>>(pos_feats1, pA, NP, NP_PAD, INV_TEMP);
    }
    {   // B: nf [D][N] -> [N][D] bf16
        dim3 grid(NN / 32, DIMD / 32, BATCH);
        conv_transpose_kernel<<<grid, dim3(32, 8)>>>(feats_view1, pB, NN, NN, 1.0f);
    }
    {
        dim3 grid(GROUPS_N, NP_PAD / 128, BATCH);   // (45, 29, 2)
        neg_gemm_kernel<<<grid, 256, SMEM_REQ>>>();
    }
    finalize_kernel<<<1, 1024>>>(out);
}

// round 9
// speedup vs baseline: 10.0906x; 1.5867x over previous
#include <cuda_runtime.h>
#include <cuda_bf16.h>
#include <cstdint>

// Problem constants (fixed shapes from the reference)
#define BATCH 2
#define DIMD  128
#define NCLS  19
#define NP    3600    // 60*60 anchors
#define NP_PAD 3712   // 29 tiles of 128
#define NN    57600   // 240*240 negatives
#define INV_TEMP 10.0f
#define GAMMA 0.75f
#define EPS 1e-8f

// GEMM config: each CTA owns one 128-row A tile and streams NTPC N-tiles of 128
#define NTPC 10
#define GROUPS_N 45   // 45*10*128 = 57600

// idesc: kind::f16, dtype F32, a/b BF16, N=128 (16<<17), M=128 (8<<24)
#define MMA_IDESC 0x08200490u

// Does this device-compilation pass have the sm_103a arch-specific features?
#if defined(__CUDA_ARCH__) && \
    (defined(__CUDA_ARCH_FEAT_SM103_ALL) || \
     (defined(__CUDA_ARCH_SPECIFIC__) && (__CUDA_ARCH_SPECIFIC__ == 1030)) || \
     (defined(__CUDA_ARCH_FAMILY_SPECIFIC__) && (__CUDA_ARCH_FAMILY_SPECIFIC__ == 1030)))
#define HAVE_TC5 1
#else
#define HAVE_TC5 0
#endif

// Scratch (device globals, no allocation)
__device__ float g_neg_logits[BATCH][NP];
__device__ float g_pos1[BATCH][NP];
__device__ float g_mask1[BATCH][NP];
__device__ int   g_labels1[BATCH][NP];
__device__ int   g_neg_labels[BATCH][NN];
__device__ __nv_bfloat16 g_Abf[BATCH][NP_PAD][DIMD];  // f1^T * 10, bf16
__device__ __nv_bfloat16 g_Bbf[BATCH][NN][DIMD];      // nf^T, bf16

// ---------------------------------------------------------------------------
// Per-anchor prep
// ---------------------------------------------------------------------------
__global__ void prep_anchor_kernel(const float* __restrict__ f1,
                                   const float* __restrict__ f2,
                                   const float* __restrict__ pl1,
                                   const float* __restrict__ pl2) {
    int p = blockIdx.x * blockDim.x + threadIdx.x;
    int b = blockIdx.y;
    if (p >= NP) return;

    const float* pl1b = pl1 + (size_t)b * NCLS * NP;
    const float* pl2b = pl2 + (size_t)b * NCLS * NP;

    float best = -1e30f; int bi = 0;
    #pragma unroll
    for (int c = 0; c < NCLS; c++) {
        float v = pl1b[c * NP + p];
        if (v > best) { best = v; bi = c; }
    }
    g_labels1[b][p] = bi;

    int mi = -1;
    #pragma unroll
    for (int c = 0; c < NCLS; c++) {
        float a = pl1b[c * NP + p];
        float q = pl2b[c * NP + p];
        if (mi < 0 && (a < q) && (q > GAMMA)) mi = c;
    }
    g_mask1[b][p] = (mi < 0) ? 0.0f : (float)mi;

    const float* f1b = f1 + (size_t)b * DIMD * NP;
    const float* f2b = f2 + (size_t)b * DIMD * NP;
    float acc = 0.0f;
    #pragma unroll 8
    for (int d = 0; d < DIMD; d++)
        acc += f1b[d * NP + p] * f2b[d * NP + p];
    g_pos1[b][p] = acc * INV_TEMP;

    g_neg_logits[b][p] = 0.0f;
}

// ---------------------------------------------------------------------------
// Per-negative prep
// ---------------------------------------------------------------------------
__global__ void prep_neg_kernel(const float* __restrict__ npl) {
    int n = blockIdx.x * blockDim.x + threadIdx.x;
    int b = blockIdx.y;
    if (n >= NN) return;
    const float* nplb = npl + (size_t)b * NCLS * NN;
    float best = -1e30f; int bi = 0;
    #pragma unroll
    for (int c = 0; c < NCLS; c++) {
        float v = nplb[c * NN + n];
        if (v > best) { best = v; bi = c; }
    }
    g_neg_labels[b][n] = bi;
}

// ---------------------------------------------------------------------------
// fp32 [D][ncols] -> bf16 [nrows_pad][D] transposed, scaled.
// ---------------------------------------------------------------------------
__global__ void conv_transpose_kernel(const float* __restrict__ src,
                                      __nv_bfloat16* __restrict__ dst,
                                      int ncols, int nrows_pad, float scale) {
    __shared__ float tile[32][33];
    int b = blockIdx.z;
    const float* s = src + (size_t)b * DIMD * ncols;
    __nv_bfloat16* d = dst + (size_t)b * nrows_pad * DIMD;
    int px = blockIdx.x * 32;
    int dy = blockIdx.y * 32;
    int tx = threadIdx.x, ty = threadIdx.y;
    #pragma unroll
    for (int i = 0; i < 4; i++) {
        int dd = dy + ty + i * 8;
        int p  = px + tx;
        float v = (p < ncols) ? s[(size_t)dd * ncols + p] : 0.0f;
        tile[ty + i * 8][tx] = v;
    }
    __syncthreads();
    #pragma unroll
    for (int i = 0; i < 4; i++) {
        int p  = px + ty + i * 8;
        int dd = dy + tx;
        if (p < nrows_pad)
            d[(size_t)p * DIMD + dd] = __float2bfloat16(tile[tx][ty + i * 8] * scale);
    }
}

// ---------------------------------------------------------------------------
// SMEM layout (bytes, from 1024-aligned base) -- tcgen05 path
//   A tile (SW128, 2 K-blocks)          [0,      32768)
//   B tiles x2 (SW128, 2 K-blocks each) [32768, 98304)
//   labels for all NTPC tiles           [98304, 103424)
//   tmem ptr                            [103424, 103428)
//   mbarriers x2                        [103432, 103448)
// ---------------------------------------------------------------------------
#define OFF_A     0u
#define OFF_B     32768u
#define OFF_NLAB  98304u      // NTPC * 128 ints = 5120 B
#define OFF_TPTR  103424u
#define OFF_MBAR  103432u
#define SMEM_REQ  (103448 + 1024)

#if HAVE_TC5
// ---------------------------------------------------------------------------
// tcgen05 helpers (sm_103a-only pass)
// ---------------------------------------------------------------------------
static constexpr uint64_t SMEM_DESC_BASE_SW128 =
    (uint64_t(2)  << 61) | (uint64_t(1) << 46) | (uint64_t(64) << 32) | (uint64_t(1) << 16);

__device__ __forceinline__ uint64_t make_desc(uint32_t saddr) {
    return SMEM_DESC_BASE_SW128 | ((uint64_t)(saddr >> 4) & 0x3FFF);
}

__device__ __forceinline__ bool elect1() {
    uint32_t p;
    asm volatile("{\n\t.reg .pred p;\n\telect.sync _|p, 0xFFFFFFFF;\n\tselp.b32 %0, 1, 0, p;\n\t}"
                 : "=r"(p));
    return p != 0;
}

__device__ __forceinline__ void mma_bf16_ss(uint32_t d, uint64_t a, uint64_t b,
                                            uint32_t en) {
    asm volatile(
        "{\n\t.reg .pred p;\n\tsetp.ne.u32 p, %4, 0;\n\t"
        "tcgen05.mma.cta_group::1.kind::f16 [%0], %1, %2, %3, {%5,%5,%5,%5}, p;\n\t}"
        :: "r"(d), "l"(a), "l"(b), "r"(MMA_IDESC), "r"(en), "r"(0u)
        : "memory");
}

__device__ __forceinline__ void mbar_init(uint32_t a, uint32_t cnt) {
    asm volatile("mbarrier.init.shared.b64 [%0], %1;" :: "r"(a), "r"(cnt) : "memory");
}
__device__ __forceinline__ void mbar_wait(uint32_t a, uint32_t ph) {
    asm volatile(
        "{\n\t.reg .pred P1;\n\t"
        "W0_%=:\n\t"
        "mbarrier.try_wait.parity.acquire.cta.shared::cta.b64 P1, [%0], %1, 0x989680;\n\t"
        "@P1 bra W1_%=;\n\t"
        "bra W0_%=;\n\t"
        "W1_%=:\n\t}"
        :: "r"(a), "r"(ph) : "memory");
}

#define TC_ALLOC(sa, n)  asm volatile("tcgen05.alloc.cta_group::1.sync.aligned.shared::cta.b32 [%0], %1;" :: "r"(sa), "r"(n) : "memory")
#define TC_RELINQ()      asm volatile("tcgen05.relinquish_alloc_permit.cta_group::1.sync.aligned;")
#define TC_DEALLOC(t, n) asm volatile("tcgen05.dealloc.cta_group::1.sync.aligned.b32 %0, %1;" :: "r"(t), "r"(n))
#define TC_COMMIT(mb)    asm volatile("tcgen05.commit.cta_group::1.mbarrier::arrive::one.shared::cluster.b64 [%0];" :: "r"(mb) : "memory")
#define TC_WAIT_LD()     asm volatile("tcgen05.wait::ld.sync.aligned;" ::: "memory")
#define TC_FENCE_AFTER() asm volatile("tcgen05.fence::after_thread_sync;" ::: "memory")
#define TC_FENCE_BEFORE() asm volatile("tcgen05.fence::before_thread_sync;" ::: "memory")
#define PROXY_FENCE()    asm volatile("fence.proxy.async.shared::cta;" ::: "memory")
#define CP_COMMIT()      asm volatile("cp.async.commit_group;" ::: "memory")
#define CP_WAIT0()       asm volatile("cp.async.wait_group 0;" ::: "memory")
#define CP_WAIT1()       asm volatile("cp.async.wait_group 1;" ::: "memory")

#define LDTM_X32(r, a) \
    asm volatile("tcgen05.ld.sync.aligned.32x32b.x32.b32 " \
        "{%0, %1, %2, %3, %4, %5, %6, %7, " \
        " %8, %9, %10, %11, %12, %13, %14, %15, " \
        " %16, %17, %18, %19, %20, %21, %22, %23, " \
        " %24, %25, %26, %27, %28, %29, %30, %31}, [%32];" \
        : "=r"((r)[0]),  "=r"((r)[1]),  "=r"((r)[2]),  "=r"((r)[3]), \
          "=r"((r)[4]),  "=r"((r)[5]),  "=r"((r)[6]),  "=r"((r)[7]), \
          "=r"((r)[8]),  "=r"((r)[9]),  "=r"((r)[10]), "=r"((r)[11]), \
          "=r"((r)[12]), "=r"((r)[13]), "=r"((r)[14]), "=r"((r)[15]), \
          "=r"((r)[16]), "=r"((r)[17]), "=r"((r)[18]), "=r"((r)[19]), \
          "=r"((r)[20]), "=r"((r)[21]), "=r"((r)[22]), "=r"((r)[23]), \
          "=r"((r)[24]), "=r"((r)[25]), "=r"((r)[26]), "=r"((r)[27]), \
          "=r"((r)[28]), "=r"((r)[29]), "=r"((r)[30]), "=r"((r)[31]) \
        : "r"(a))

// cp.async a [128 rows x 128 bf16] row-major global tile into K-blocked
// SW128 SMEM: two blocks of [128 rows x 64 bf16] (128B rows, XOR swizzle).
__device__ __forceinline__ void cp_tile128(const __nv_bfloat16* __restrict__ g,
                                           uint32_t s_base, int tid) {
    #pragma unroll
    for (int i = 0; i < 8; i++) {
        int q = tid + i * 256;         // 16B-chunk index, 2048 total
        int r = q >> 4;                // row 0..127
        int c = q & 15;                // chunk 0..15
        int blk = c >> 3;
        int cc  = (c & 7) ^ (r & 7);
        uint32_t sa = s_base + blk * 16384u + (uint32_t)r * 128u + (uint32_t)cc * 16u;
        const void* ga = (const void*)(g + (size_t)r * 128 + c * 8);
        asm volatile("cp.async.cg.shared.global [%0], [%1], 16;"
                     :: "r"(sa), "l"(ga) : "memory");
    }
}
#endif  // HAVE_TC5

#if !HAVE_TC5
// ---------------------------------------------------------------------------
// Fallback helpers: mma.sync m16n8k16 bf16 (compiles on any >= sm_80 target)
// ---------------------------------------------------------------------------
__device__ __forceinline__ void ldmx4(uint32_t* r, uint32_t saddr) {
    asm volatile("ldmatrix.sync.aligned.m8n8.x4.shared.b16 {%0,%1,%2,%3}, [%4];"
                 : "=r"(r[0]), "=r"(r[1]), "=r"(r[2]), "=r"(r[3]) : "r"(saddr));
}
__device__ __forceinline__ void mma16816(float* c, const uint32_t* a, const uint32_t* b) {
    asm volatile("mma.sync.aligned.m16n8k16.row.col.f32.bf16.bf16.f32 "
                 "{%0,%1,%2,%3}, {%4,%5,%6,%7}, {%8,%9}, {%0,%1,%2,%3};"
                 : "+f"(c[0]), "+f"(c[1]), "+f"(c[2]), "+f"(c[3])
                 : "r"(a[0]), "r"(a[1]), "r"(a[2]), "r"(a[3]), "r"(b[0]), "r"(b[1]));
}
// swizzled element offset in a flat [r][128] bf16 tile (16B-chunk XOR swizzle)
__device__ __forceinline__ int swz(int r, int k) {
    return r * 128 + ((((k) >> 3) ^ (r & 7)) << 3) + (k & 7);
}
#endif  // !HAVE_TC5

// ---------------------------------------------------------------------------
// GEMM + fused masked-exp row-sum epilogue. One kernel name, two bodies:
// tcgen05 (sm_103a cubin) or mma.sync (virtual-arch / JIT fallback).
// Grid: (GROUPS_N, NP_PAD/128, BATCH), 256 threads, SMEM_REQ dynamic smem.
// ---------------------------------------------------------------------------
__global__ __launch_bounds__(256)
void neg_gemm_kernel() {
    extern __shared__ __align__(16) uint8_t dynsmem[];
    uint8_t* smem = (uint8_t*)(((uintptr_t)dynsmem + 1023) & ~(uintptr_t)1023);

    const int b      = blockIdx.z;
    const int p0     = blockIdx.y * 128;
    const int n_base = blockIdx.x * (NTPC * 128);
    const int tid    = threadIdx.x;
    const int wid    = tid >> 5;
    const int lane   = tid & 31;

#if HAVE_TC5
    // ======================= tcgen05 pipelined path =======================
    const uint32_t sb    = (uint32_t)__cvta_generic_to_shared(smem);
    const uint32_t mbar0 = sb + OFF_MBAR;
    const uint32_t mbar1 = sb + OFF_MBAR + 8;
    int* nlabAll = (int*)(smem + OFF_NLAB);

    if (wid == 0) {
        TC_ALLOC(sb + OFF_TPTR, 256u);
        TC_RELINQ();
    }
    if (tid == 0) { mbar_init(mbar0, 1); mbar_init(mbar1, 1); }

    // prologue: async-load A + B0 (group 0), B1 (group 1); labels for all tiles
    cp_tile128(&g_Abf[b][p0][0], sb + OFF_A, tid);
    cp_tile128(&g_Bbf[b][n_base][0], sb + OFF_B, tid);
    CP_COMMIT();
    cp_tile128(&g_Bbf[b][n_base + 128][0], sb + OFF_B + 32768u, tid);
    CP_COMMIT();
    #pragma unroll
    for (int i = 0; i < NTPC * 128 / 256; i++)
        nlabAll[tid + i * 256] = g_neg_labels[b][n_base + tid + i * 256];

    CP_WAIT1();        // A + B0 resident
    PROXY_FENCE();
    __syncthreads();

    const uint32_t tmem_base = *reinterpret_cast<uint32_t*>(smem + OFF_TPTR);
    const uint64_t adesc = make_desc(sb + OFF_A);

    // issue MMA for tile 0
    if (wid == 0) {
        TC_FENCE_AFTER();
        if (elect1()) {
            uint64_t bdesc = make_desc(sb + OFF_B);
            #pragma unroll
            for (int kk = 0; kk < 8; kk++) {
                uint64_t koff = (uint64_t)((kk >> 2) * 1024 + (kk & 3) * 2);
                mma_bf16_ss(tmem_base, adesc + koff, bdesc + koff, kk > 0);
            }
            TC_COMMIT(mbar0);
        }
    }

    const int myrow = (wid & 3) * 32 + lane;
    const int myp   = p0 + myrow;
    const int lp    = (myp < NP) ? g_labels1[b][myp] : -1;
    float rs0 = 0.0f, rs1 = 0.0f;
    const int cbase = (wid >> 2) * 64;  // warpgroup column split

    for (int nt = 1; nt <= NTPC; nt++) {
        const int prev = nt - 1;

        // MMA prev done (issued one epilogue ago -> fast-path wait)
        mbar_wait((prev & 1) ? mbar1 : mbar0, (prev >> 1) & 1);

        if (nt < NTPC) {
            // prefetch B[nt+1] into the buffer MMA prev just released
            if (nt + 1 < NTPC) {
                cp_tile128(&g_Bbf[b][n_base + (nt + 1) * 128][0],
                           sb + OFF_B + (uint32_t)((nt + 1) & 1) * 32768u, tid);
                CP_COMMIT();
                CP_WAIT1();      // B[nt] resident
            } else {
                CP_WAIT0();      // B[nt] resident, no more prefetch
            }
            PROXY_FENCE();
        }
        __syncthreads();

        if (nt < NTPC && wid == 0) {
            TC_FENCE_AFTER();
            if (elect1()) {
                uint64_t bdesc = make_desc(sb + OFF_B + (uint32_t)(nt & 1) * 32768u);
                uint32_t dtm = tmem_base + (nt & 1) * 128;
                #pragma unroll
                for (int kk = 0; kk < 8; kk++) {
                    uint64_t koff = (uint64_t)((kk >> 2) * 1024 + (kk & 3) * 2);
                    mma_bf16_ss(dtm, adesc + koff, bdesc + koff, kk > 0);
                }
                TC_COMMIT((nt & 1) ? mbar1 : mbar0);
            }
        }

        // ---- epilogue tile prev (overlaps MMA nt + prefetch B nt+1) ----
        TC_FENCE_AFTER();
        const int* nl = nlabAll + prev * 128;
        const uint32_t dtm_prev = tmem_base + (prev & 1) * 128;
        #pragma unroll
        for (int ch = 0; ch < 2; ch++) {
            const int c0 = cbase + ch * 32;
            uint32_t r[32];
            LDTM_X32(r, dtm_prev + c0);
            TC_WAIT_LD();
            #pragma unroll
            for (int j = 0; j < 32; j += 2) {
                float e0 = __expf(__uint_as_float(r[j]));
                float e1 = __expf(__uint_as_float(r[j + 1]));
                rs0 += (lp != nl[c0 + j])     ? e0 : 0.0f;
                rs1 += (lp != nl[c0 + j + 1]) ? e1 : 0.0f;
            }
        }
        TC_FENCE_BEFORE();
    }

    if (myp < NP)
        atomicAdd(&g_neg_logits[b][myp], rs0 + rs1);

    __syncthreads();
    if (wid == 0) TC_DEALLOC(tmem_base, 256u);

#else
    // ======================= mma.sync fallback path =======================
    __nv_bfloat16* Asm = (__nv_bfloat16*)smem;             // 32KB (flat [128][128] swz)
    __nv_bfloat16* Bsm = (__nv_bfloat16*)(smem + 32768u);  // 32KB
    int* nlab = (int*)(smem + 65536u);                     // 128 ints

    const int wm = wid & 3;    // m sub-block (32 rows)
    const int wn = wid >> 2;   // n sub-block (64 cols)

    const __nv_bfloat16* Ag = &g_Abf[b][p0][0];
    #pragma unroll
    for (int i = 0; i < 8; i++) {
        int q = tid + i * 256;
        int r = q >> 4;
        int c = q & 15;
        uint4 v = *reinterpret_cast<const uint4*>(Ag + (size_t)r * 128 + c * 8);
        int sc = c ^ (r & 7);
        *reinterpret_cast<uint4*>(Asm + r * 128 + sc * 8) = v;
    }

    int lp2[2][2];
    #pragma unroll
    for (int mi = 0; mi < 2; mi++) {
        int base = p0 + wm * 32 + mi * 16 + (lane >> 2);
        lp2[mi][0] = (base     < NP) ? g_labels1[b][base]     : -1;
        lp2[mi][1] = (base + 8 < NP) ? g_labels1[b][base + 8] : -1;
    }
    float rs[2][2] = {{0.f, 0.f}, {0.f, 0.f}};

    const uint32_t asmb = (uint32_t)__cvta_generic_to_shared(Asm);
    const uint32_t bsmb = (uint32_t)__cvta_generic_to_shared(Bsm);

    for (int nt = 0; nt < NTPC; nt++) {
        const int n0 = n_base + nt * 128;
        __syncthreads();
        const __nv_bfloat16* Bg = &g_Bbf[b][n0][0];
        #pragma unroll
        for (int i = 0; i < 8; i++) {
            int q = tid + i * 256;
            int r = q >> 4;
            int c = q & 15;
            uint4 v = *reinterpret_cast<const uint4*>(Bg + (size_t)r * 128 + c * 8);
            int sc = c ^ (r & 7);
            *reinterpret_cast<uint4*>(Bsm + r * 128 + sc * 8) = v;
        }
        if (tid < 128) nlab[tid] = g_neg_labels[b][n0 + tid];
        __syncthreads();

        float acc[2][8][4];
        #pragma unroll
        for (int mi = 0; mi < 2; mi++)
            #pragma unroll
            for (int ni = 0; ni < 8; ni++)
                #pragma unroll
                for (int x = 0; x < 4; x++) acc[mi][ni][x] = 0.0f;

        #pragma unroll
        for (int kk = 0; kk < 8; kk++) {
            const int k0 = kk * 16;
            uint32_t afr[2][4];
            #pragma unroll
            for (int mi = 0; mi < 2; mi++) {
                int row = wm * 32 + mi * 16 + (lane & 7) + 8 * ((lane >> 3) & 1);
                int k8  = k0 + 8 * (lane >> 4);
                ldmx4(afr[mi], asmb + 2 * swz(row, k8));
            }
            uint32_t bfr[8][2];
            #pragma unroll
            for (int nj = 0; nj < 4; nj++) {
                int nrow = wn * 64 + nj * 16 + (lane & 7) + 8 * (lane >> 4);
                int k8   = k0 + 8 * ((lane >> 3) & 1);
                uint32_t r4[4];
                ldmx4(r4, bsmb + 2 * swz(nrow, k8));
                bfr[nj * 2][0]     = r4[0]; bfr[nj * 2][1]     = r4[1];
                bfr[nj * 2 + 1][0] = r4[2]; bfr[nj * 2 + 1][1] = r4[3];
            }
            #pragma unroll
            for (int mi = 0; mi < 2; mi++)
                #pragma unroll
                for (int ni = 0; ni < 8; ni++)
                    mma16816(acc[mi][ni], afr[mi], bfr[ni]);
        }

        #pragma unroll
        for (int ni = 0; ni < 8; ni++) {
            int c0  = wn * 64 + ni * 8 + 2 * (lane & 3);
            int ln0 = nlab[c0];
            int ln1 = nlab[c0 + 1];
            #pragma unroll
            for (int mi = 0; mi < 2; mi++) {
                float e0 = __expf(acc[mi][ni][0]);
                float e1 = __expf(acc[mi][ni][1]);
                float e2 = __expf(acc[mi][ni][2]);
                float e3 = __expf(acc[mi][ni][3]);
                rs[mi][0] += (lp2[mi][0] != ln0 ? e0 : 0.f) + (lp2[mi][0] != ln1 ? e1 : 0.f);
                rs[mi][1] += (lp2[mi][1] != ln0 ? e2 : 0.f) + (lp2[mi][1] != ln1 ? e3 : 0.f);
            }
        }
    }

    #pragma unroll
    for (int mi = 0; mi < 2; mi++)
        #pragma unroll
        for (int h = 0; h < 2; h++) {
            float s = rs[mi][h];
            s += __shfl_xor_sync(0xffffffffu, s, 1);
            s += __shfl_xor_sync(0xffffffffu, s, 2);
            int p = p0 + wm * 32 + mi * 16 + (lane >> 2) + h * 8;
            if ((lane & 3) == 0 && p < NP)
                atomicAdd(&g_neg_logits[b][p], s);
        }
#endif
}

// ---------------------------------------------------------------------------
// Finalize (fast intrinsics; tiny kernel)
// ---------------------------------------------------------------------------
__global__ void finalize_kernel(float* __restrict__ out) {
    __shared__ float s_num[1024];
    __shared__ float s_den[1024];
    const int tid = threadIdx.x;
    float total = 0.0f;

    for (int b = 0; b < BATCH; b++) {
        float num = 0.0f, den = 0.0f;
        for (int p = tid; p < NP; p += 1024) {
            float pe  = __expf(g_pos1[b][p]);
            float neg = g_neg_logits[b][p];
            float lossn = -__logf(pe / (pe + neg + EPS) + EPS);
            float m = g_mask1[b][p];
            num += m * lossn;
            den += m;
        }
        s_num[tid] = num; s_den[tid] = den;
        __syncthreads();
        for (int s = 512; s > 0; s >>= 1) {
            if (tid < s) { s_num[tid] += s_num[tid + s]; s_den[tid] += s_den[tid + s]; }
            __syncthreads();
        }
        if (tid == 0) total += s_num[0] / (s_den[0] + EPS);
        __syncthreads();
    }
    if (tid == 0) out[0] = 0.1f * total;
}

// ---------------------------------------------------------------------------
extern "C" void kernel_launch(void* const* d_in, const int* in_sizes, int n_in,
                              void* d_out, int out_size) {
    const float* feats_view1 = (const float*)d_in[0];  // [2,128,240,240]
    const float* pos_feats1  = (const float*)d_in[1];  // [2,128,60,60]
    const float* pos_feats2  = (const float*)d_in[2];  // [2,128,60,60]
    const float* plog1       = (const float*)d_in[3];  // [2,19,60,60]
    const float* plog2       = (const float*)d_in[4];  // [2,19,60,60]
    const float* neg_plog    = (const float*)d_in[5];  // [2,19,240,240]
    float* out = (float*)d_out;

    static __nv_bfloat16* pA = nullptr;
    static __nv_bfloat16* pB = nullptr;
    if (!pA) { cudaGetSymbolAddress((void**)&pA, g_Abf); }
    if (!pB) { cudaGetSymbolAddress((void**)&pB, g_Bbf); }

    static bool attr_set = false;
    if (!attr_set) {
        cudaFuncSetAttribute(neg_gemm_kernel,
                             cudaFuncAttributeMaxDynamicSharedMemorySize, SMEM_REQ);
        attr_set = true;
    }

    {
        dim3 grid((NP + 255) / 256, BATCH);
        prep_anchor_kernel<<<grid, 256>>>(pos_feats1, pos_feats2, plog1, plog2);
    }
    {
        dim3 grid((NN + 255) / 256, BATCH);
        prep_neg_kernel<<<grid, 256>>>(neg_plog);
    }
    {   // A: f1 [D][P] -> [P_pad][D] bf16, prescaled by 1/TEMP
        dim3 grid(NP_PAD / 32, DIMD / 32, BATCH);
        conv_transpose_kernel<<<grid, dim3(32, 8)>>>(pos_feats1, pA, NP, NP_PAD, INV_TEMP);
    }
    {   // B: nf [D][N] -> [N][D] bf16
        dim3 grid(NN / 32, DIMD / 32, BATCH);
        conv_transpose_kernel<<<grid, dim3(32, 8)>>>(feats_view1, pB, NN, NN, 1.0f);
    }
    {
        dim3 grid(GROUPS_N, NP_PAD / 128, BATCH);   // (45, 29, 2)
        neg_gemm_kernel<<<grid, 256, SMEM_REQ>>>();
    }
    finalize_kernel<<<1, 1024>>>(out);
}

// round 12
// speedup vs baseline: 12.2966x; 1.2186x over previous
#include <cuda_runtime.h>
#include <cuda_fp16.h>
#include <cstdint>

// Problem constants (fixed shapes from the reference)
#define BATCH 2
#define DIMD  128
#define NCLS  19
#define NP    3600    // 60*60 anchors
#define NP_PAD 3712   // 29 tiles of 128
#define NN    57600   // 240*240 negatives
#define INV_TEMP 10.0f
// A is prescaled by 10*log2(e) so the epilogue uses a single EX2 per element.
#define A_SCALE 14.4269504088896340736f
#define GAMMA 0.75f
#define EPS 1e-8f

// GEMM config: each CTA owns one 128-row A tile and streams NTPC N-tiles of 128
#define NTPC 18
#define GROUPS_N 25   // 25*18*128 = 57600

// idesc: kind::f16, dtype F32 (1<<4), a/b F16 (0), N=128 (16<<17), M=128 (8<<24)
#define MMA_IDESC 0x08200010u

// Does this device-compilation pass have the sm_103a arch-specific features?
#if defined(__CUDA_ARCH__) && \
    (defined(__CUDA_ARCH_FEAT_SM103_ALL) || \
     (defined(__CUDA_ARCH_SPECIFIC__) && (__CUDA_ARCH_SPECIFIC__ == 1030)) || \
     (defined(__CUDA_ARCH_FAMILY_SPECIFIC__) && (__CUDA_ARCH_FAMILY_SPECIFIC__ == 1030)))
#define HAVE_TC5 1
#else
#define HAVE_TC5 0
#endif

// Scratch (device globals, no allocation)
__device__ float g_neg_logits[BATCH][NP];
__device__ float g_pos1[BATCH][NP];
__device__ float g_mask1[BATCH][NP];
__device__ int   g_labels1[BATCH][NP];
__device__ int   g_neg_labels[BATCH][NN];
__device__ __half g_Ah[BATCH][NP_PAD][DIMD];  // f1^T * 10*log2(e), f16
__device__ __half g_Bh[BATCH][NN][DIMD];      // nf^T, f16

__device__ __forceinline__ float ex2f(float x) {
    float r;
    asm("ex2.approx.ftz.f32 %0, %1;" : "=f"(r) : "f"(x));
    return r;
}

// ---------------------------------------------------------------------------
// Per-anchor prep
// ---------------------------------------------------------------------------
__global__ void prep_anchor_kernel(const float* __restrict__ f1,
                                   const float* __restrict__ f2,
                                   const float* __restrict__ pl1,
                                   const float* __restrict__ pl2) {
    int p = blockIdx.x * blockDim.x + threadIdx.x;
    int b = blockIdx.y;
    if (p >= NP) return;

    const float* pl1b = pl1 + (size_t)b * NCLS * NP;
    const float* pl2b = pl2 + (size_t)b * NCLS * NP;

    float best = -1e30f; int bi = 0;
    #pragma unroll
    for (int c = 0; c < NCLS; c++) {
        float v = pl1b[c * NP + p];
        if (v > best) { best = v; bi = c; }
    }
    g_labels1[b][p] = bi;

    int mi = -1;
    #pragma unroll
    for (int c = 0; c < NCLS; c++) {
        float a = pl1b[c * NP + p];
        float q = pl2b[c * NP + p];
        if (mi < 0 && (a < q) && (q > GAMMA)) mi = c;
    }
    g_mask1[b][p] = (mi < 0) ? 0.0f : (float)mi;

    const float* f1b = f1 + (size_t)b * DIMD * NP;
    const float* f2b = f2 + (size_t)b * DIMD * NP;
    float acc = 0.0f;
    #pragma unroll 8
    for (int d = 0; d < DIMD; d++)
        acc += f1b[d * NP + p] * f2b[d * NP + p];
    g_pos1[b][p] = acc * INV_TEMP;

    g_neg_logits[b][p] = 0.0f;
}

// ---------------------------------------------------------------------------
// Per-negative prep
// ---------------------------------------------------------------------------
__global__ void prep_neg_kernel(const float* __restrict__ npl) {
    int n = blockIdx.x * blockDim.x + threadIdx.x;
    int b = blockIdx.y;
    if (n >= NN) return;
    const float* nplb = npl + (size_t)b * NCLS * NN;
    float best = -1e30f; int bi = 0;
    #pragma unroll
    for (int c = 0; c < NCLS; c++) {
        float v = nplb[c * NN + n];
        if (v > best) { best = v; bi = c; }
    }
    g_neg_labels[b][n] = bi;
}

// ---------------------------------------------------------------------------
// fp32 [D][ncols] -> f16 [nrows_pad][D] transposed, scaled.
// ---------------------------------------------------------------------------
__global__ void conv_transpose_kernel(const float* __restrict__ src,
                                      __half* __restrict__ dst,
                                      int ncols, int nrows_pad, float scale) {
    __shared__ float tile[32][33];
    int b = blockIdx.z;
    const float* s = src + (size_t)b * DIMD * ncols;
    __half* d = dst + (size_t)b * nrows_pad * DIMD;
    int px = blockIdx.x * 32;
    int dy = blockIdx.y * 32;
    int tx = threadIdx.x, ty = threadIdx.y;
    #pragma unroll
    for (int i = 0; i < 4; i++) {
        int dd = dy + ty + i * 8;
        int p  = px + tx;
        float v = (p < ncols) ? s[(size_t)dd * ncols + p] : 0.0f;
        tile[ty + i * 8][tx] = v;
    }
    __syncthreads();
    #pragma unroll
    for (int i = 0; i < 4; i++) {
        int p  = px + ty + i * 8;
        int dd = dy + tx;
        if (p < nrows_pad)
            d[(size_t)p * DIMD + dd] = __float2half(tile[tx][ty + i * 8] * scale);
    }
}

// ---------------------------------------------------------------------------
// SMEM layout (bytes, from 1024-aligned base) -- tcgen05 path
//   A tile (SW128, 2 K-blocks)          [0,      32768)
//   B tiles x2 (SW128, 2 K-blocks each) [32768, 98304)
//   labels for all NTPC tiles           [98304, 107520)   18*128 ints
//   tmem ptr                            [107520, 107524)
//   mbarriers x2                        [107528, 107544)
// ---------------------------------------------------------------------------
#define OFF_A     0u
#define OFF_B     32768u
#define OFF_NLAB  98304u
#define OFF_TPTR  107520u
#define OFF_MBAR  107528u
#define SMEM_REQ  (107544 + 1024)

#if HAVE_TC5
// ---------------------------------------------------------------------------
// tcgen05 helpers (sm_103a-only pass)
// ---------------------------------------------------------------------------
static constexpr uint64_t SMEM_DESC_BASE_SW128 =
    (uint64_t(2)  << 61) | (uint64_t(1) << 46) | (uint64_t(64) << 32) | (uint64_t(1) << 16);

__device__ __forceinline__ uint64_t make_desc(uint32_t saddr) {
    return SMEM_DESC_BASE_SW128 | ((uint64_t)(saddr >> 4) & 0x3FFF);
}

__device__ __forceinline__ bool elect1() {
    uint32_t p;
    asm volatile("{\n\t.reg .pred p;\n\telect.sync _|p, 0xFFFFFFFF;\n\tselp.b32 %0, 1, 0, p;\n\t}"
                 : "=r"(p));
    return p != 0;
}

__device__ __forceinline__ void mma_f16_ss(uint32_t d, uint64_t a, uint64_t b,
                                           uint32_t en) {
    asm volatile(
        "{\n\t.reg .pred p;\n\tsetp.ne.u32 p, %4, 0;\n\t"
        "tcgen05.mma.cta_group::1.kind::f16 [%0], %1, %2, %3, {%5,%5,%5,%5}, p;\n\t}"
        :: "r"(d), "l"(a), "l"(b), "r"(MMA_IDESC), "r"(en), "r"(0u)
        : "memory");
}

__device__ __forceinline__ void mbar_init(uint32_t a, uint32_t cnt) {
    asm volatile("mbarrier.init.shared.b64 [%0], %1;" :: "r"(a), "r"(cnt) : "memory");
}
__device__ __forceinline__ void mbar_wait(uint32_t a, uint32_t ph) {
    asm volatile(
        "{\n\t.reg .pred P1;\n\t"
        "W0_%=:\n\t"
        "mbarrier.try_wait.parity.acquire.cta.shared::cta.b64 P1, [%0], %1, 0x989680;\n\t"
        "@P1 bra W1_%=;\n\t"
        "bra W0_%=;\n\t"
        "W1_%=:\n\t}"
        :: "r"(a), "r"(ph) : "memory");
}

#define TC_ALLOC(sa, n)  asm volatile("tcgen05.alloc.cta_group::1.sync.aligned.shared::cta.b32 [%0], %1;" :: "r"(sa), "r"(n) : "memory")
#define TC_RELINQ()      asm volatile("tcgen05.relinquish_alloc_permit.cta_group::1.sync.aligned;")
#define TC_DEALLOC(t, n) asm volatile("tcgen05.dealloc.cta_group::1.sync.aligned.b32 %0, %1;" :: "r"(t), "r"(n))
#define TC_COMMIT(mb)    asm volatile("tcgen05.commit.cta_group::1.mbarrier::arrive::one.shared::cluster.b64 [%0];" :: "r"(mb) : "memory")
#define TC_WAIT_LD()     asm volatile("tcgen05.wait::ld.sync.aligned;" ::: "memory")
#define TC_FENCE_AFTER() asm volatile("tcgen05.fence::after_thread_sync;" ::: "memory")
#define TC_FENCE_BEFORE() asm volatile("tcgen05.fence::before_thread_sync;" ::: "memory")
#define PROXY_FENCE()    asm volatile("fence.proxy.async.shared::cta;" ::: "memory")
#define CP_COMMIT()      asm volatile("cp.async.commit_group;" ::: "memory")
#define CP_WAIT0()       asm volatile("cp.async.wait_group 0;" ::: "memory")
#define CP_WAIT1()       asm volatile("cp.async.wait_group 1;" ::: "memory")

#define LDTM_X32(r, a) \
    asm volatile("tcgen05.ld.sync.aligned.32x32b.x32.b32 " \
        "{%0, %1, %2, %3, %4, %5, %6, %7, " \
        " %8, %9, %10, %11, %12, %13, %14, %15, " \
        " %16, %17, %18, %19, %20, %21, %22, %23, " \
        " %24, %25, %26, %27, %28, %29, %30, %31}, [%32];" \
        : "=r"((r)[0]),  "=r"((r)[1]),  "=r"((r)[2]),  "=r"((r)[3]), \
          "=r"((r)[4]),  "=r"((r)[5]),  "=r"((r)[6]),  "=r"((r)[7]), \
          "=r"((r)[8]),  "=r"((r)[9]),  "=r"((r)[10]), "=r"((r)[11]), \
          "=r"((r)[12]), "=r"((r)[13]), "=r"((r)[14]), "=r"((r)[15]), \
          "=r"((r)[16]), "=r"((r)[17]), "=r"((r)[18]), "=r"((r)[19]), \
          "=r"((r)[20]), "=r"((r)[21]), "=r"((r)[22]), "=r"((r)[23]), \
          "=r"((r)[24]), "=r"((r)[25]), "=r"((r)[26]), "=r"((r)[27]), \
          "=r"((r)[28]), "=r"((r)[29]), "=r"((r)[30]), "=r"((r)[31]) \
        : "r"(a))

// cp.async a [128 rows x 128 f16] row-major global tile into K-blocked
// SW128 SMEM: two blocks of [128 rows x 64 f16] (128B rows, XOR swizzle).
__device__ __forceinline__ void cp_tile128(const __half* __restrict__ g,
                                           uint32_t s_base, int tid) {
    #pragma unroll
    for (int i = 0; i < 8; i++) {
        int q = tid + i * 256;         // 16B-chunk index, 2048 total
        int r = q >> 4;                // row 0..127
        int c = q & 15;                // chunk 0..15
        int blk = c >> 3;
        int cc  = (c & 7) ^ (r & 7);
        uint32_t sa = s_base + blk * 16384u + (uint32_t)r * 128u + (uint32_t)cc * 16u;
        const void* ga = (const void*)(g + (size_t)r * 128 + c * 8);
        asm volatile("cp.async.cg.shared.global [%0], [%1], 16;"
                     :: "r"(sa), "l"(ga) : "memory");
    }
}
#endif  // HAVE_TC5

#if !HAVE_TC5
// ---------------------------------------------------------------------------
// Fallback helpers: mma.sync m16n8k16 f16 (compiles on any >= sm_80 target)
// ---------------------------------------------------------------------------
__device__ __forceinline__ void ldmx4(uint32_t* r, uint32_t saddr) {
    asm volatile("ldmatrix.sync.aligned.m8n8.x4.shared.b16 {%0,%1,%2,%3}, [%4];"
                 : "=r"(r[0]), "=r"(r[1]), "=r"(r[2]), "=r"(r[3]) : "r"(saddr));
}
__device__ __forceinline__ void mma16816(float* c, const uint32_t* a, const uint32_t* b) {
    asm volatile("mma.sync.aligned.m16n8k16.row.col.f32.f16.f16.f32 "
                 "{%0,%1,%2,%3}, {%4,%5,%6,%7}, {%8,%9}, {%0,%1,%2,%3};"
                 : "+f"(c[0]), "+f"(c[1]), "+f"(c[2]), "+f"(c[3])
                 : "r"(a[0]), "r"(a[1]), "r"(a[2]), "r"(a[3]), "r"(b[0]), "r"(b[1]));
}
// swizzled element offset in a flat [r][128] f16 tile (16B-chunk XOR swizzle)
__device__ __forceinline__ int swz(int r, int k) {
    return r * 128 + ((((k) >> 3) ^ (r & 7)) << 3) + (k & 7);
}
#endif  // !HAVE_TC5

// ---------------------------------------------------------------------------
// GEMM + fused masked-exp row-sum epilogue. One kernel name, two bodies:
// tcgen05 (sm_103a cubin) or mma.sync (virtual-arch / JIT fallback).
// Grid: (GROUPS_N, NP_PAD/128, BATCH), 256 threads, SMEM_REQ dynamic smem.
// ---------------------------------------------------------------------------
__global__ __launch_bounds__(256, 2)
void neg_gemm_kernel() {
    extern __shared__ __align__(16) uint8_t dynsmem[];
    uint8_t* smem = (uint8_t*)(((uintptr_t)dynsmem + 1023) & ~(uintptr_t)1023);

    const int b      = blockIdx.z;
    const int p0     = blockIdx.y * 128;
    const int n_base = blockIdx.x * (NTPC * 128);
    const int tid    = threadIdx.x;
    const int wid    = tid >> 5;
    const int lane   = tid & 31;

#if HAVE_TC5
    // ======================= tcgen05 pipelined path =======================
    // D accumulator fp32: 128 TMEM cols per tile; double buffer at 0 / 128.
    const uint32_t sb    = (uint32_t)__cvta_generic_to_shared(smem);
    const uint32_t mbar0 = sb + OFF_MBAR;
    const uint32_t mbar1 = sb + OFF_MBAR + 8;
    int* nlabAll = (int*)(smem + OFF_NLAB);

    if (wid == 0) {
        TC_ALLOC(sb + OFF_TPTR, 256u);
        TC_RELINQ();
    }
    if (tid == 0) { mbar_init(mbar0, 1); mbar_init(mbar1, 1); }

    // prologue: async-load A + B0 (group 0), B1 (group 1); labels for all tiles
    cp_tile128(&g_Ah[b][p0][0], sb + OFF_A, tid);
    cp_tile128(&g_Bh[b][n_base][0], sb + OFF_B, tid);
    CP_COMMIT();
    cp_tile128(&g_Bh[b][n_base + 128][0], sb + OFF_B + 32768u, tid);
    CP_COMMIT();
    #pragma unroll
    for (int i = 0; i < NTPC * 128 / 256; i++)
        nlabAll[tid + i * 256] = g_neg_labels[b][n_base + tid + i * 256];

    CP_WAIT1();        // A + B0 resident
    PROXY_FENCE();
    __syncthreads();

    const uint32_t tmem_base = *reinterpret_cast<uint32_t*>(smem + OFF_TPTR);
    const uint64_t adesc = make_desc(sb + OFF_A);

    // issue MMA for tile 0
    if (wid == 0) {
        TC_FENCE_AFTER();
        if (elect1()) {
            uint64_t bdesc = make_desc(sb + OFF_B);
            #pragma unroll
            for (int kk = 0; kk < 8; kk++) {
                uint64_t koff = (uint64_t)((kk >> 2) * 1024 + (kk & 3) * 2);
                mma_f16_ss(tmem_base, adesc + koff, bdesc + koff, kk > 0);
            }
            TC_COMMIT(mbar0);
        }
    }

    const int myrow = (wid & 3) * 32 + lane;
    const int myp   = p0 + myrow;
    const int lp    = (myp < NP) ? g_labels1[b][myp] : -1;
    float rs0 = 0.0f, rs1 = 0.0f;
    const int cbase = (wid >> 2) * 64;  // warpgroup n-column split

    for (int nt = 1; nt <= NTPC; nt++) {
        const int prev = nt - 1;

        // MMA prev done (issued one epilogue ago -> fast-path wait)
        mbar_wait((prev & 1) ? mbar1 : mbar0, (prev >> 1) & 1);

        if (nt < NTPC) {
            // prefetch B[nt+1] into the buffer MMA prev just released
            if (nt + 1 < NTPC) {
                cp_tile128(&g_Bh[b][n_base + (nt + 1) * 128][0],
                           sb + OFF_B + (uint32_t)((nt + 1) & 1) * 32768u, tid);
                CP_COMMIT();
                CP_WAIT1();      // B[nt] resident
            } else {
                CP_WAIT0();      // B[nt] resident, no more prefetch
            }
            PROXY_FENCE();
        }
        __syncthreads();

        if (nt < NTPC && wid == 0) {
            TC_FENCE_AFTER();
            if (elect1()) {
                uint64_t bdesc = make_desc(sb + OFF_B + (uint32_t)(nt & 1) * 32768u);
                uint32_t dtm = tmem_base + (nt & 1) * 128;
                #pragma unroll
                for (int kk = 0; kk < 8; kk++) {
                    uint64_t koff = (uint64_t)((kk >> 2) * 1024 + (kk & 3) * 2);
                    mma_f16_ss(dtm, adesc + koff, bdesc + koff, kk > 0);
                }
                TC_COMMIT((nt & 1) ? mbar1 : mbar0);
            }
        }

        // ---- epilogue tile prev (overlaps MMA nt + prefetch B nt+1) ----
        // Pipelined: LDTM chunk0, wait, issue LDTM chunk1, process chunk0
        // (hiding chunk1's TMEM latency under chunk0's MUFU exps), wait,
        // process chunk1. Scores are in log2 domain -> single EX2 each.
        TC_FENCE_AFTER();
        const int* nl = nlabAll + prev * 128;
        const uint32_t dtm_prev = tmem_base + (prev & 1) * 128;
        uint32_t r0[32], r1[32];
        LDTM_X32(r0, dtm_prev + cbase);
        TC_WAIT_LD();
        LDTM_X32(r1, dtm_prev + cbase + 32);
        #pragma unroll
        for (int j = 0; j < 32; j += 2) {
            float e0 = ex2f(__uint_as_float(r0[j]));
            float e1 = ex2f(__uint_as_float(r0[j + 1]));
            rs0 += (lp != nl[cbase + j])     ? e0 : 0.0f;
            rs1 += (lp != nl[cbase + j + 1]) ? e1 : 0.0f;
        }
        TC_WAIT_LD();
        #pragma unroll
        for (int j = 0; j < 32; j += 2) {
            float e0 = ex2f(__uint_as_float(r1[j]));
            float e1 = ex2f(__uint_as_float(r1[j + 1]));
            rs0 += (lp != nl[cbase + 32 + j])     ? e0 : 0.0f;
            rs1 += (lp != nl[cbase + 32 + j + 1]) ? e1 : 0.0f;
        }
        TC_FENCE_BEFORE();
    }

    if (myp < NP)
        atomicAdd(&g_neg_logits[b][myp], rs0 + rs1);

    __syncthreads();
    if (wid == 0) TC_DEALLOC(tmem_base, 256u);

#else
    // ======================= mma.sync fallback path =======================
    __half* Asm = (__half*)smem;             // 32KB (flat [128][128] swz)
    __half* Bsm = (__half*)(smem + 32768u);  // 32KB
    int* nlab = (int*)(smem + 65536u);       // 128 ints

    const int wm = wid & 3;    // m sub-block (32 rows)
    const int wn = wid >> 2;   // n sub-block (64 cols)

    const __half* Ag = &g_Ah[b][p0][0];
    #pragma unroll
    for (int i = 0; i < 8; i++) {
        int q = tid + i * 256;
        int r = q >> 4;
        int c = q & 15;
        uint4 v = *reinterpret_cast<const uint4*>(Ag + (size_t)r * 128 + c * 8);
        int sc = c ^ (r & 7);
        *reinterpret_cast<uint4*>(Asm + r * 128 + sc * 8) = v;
    }

    int lp2[2][2];
    #pragma unroll
    for (int mi = 0; mi < 2; mi++) {
        int base = p0 + wm * 32 + mi * 16 + (lane >> 2);
        lp2[mi][0] = (base     < NP) ? g_labels1[b][base]     : -1;
        lp2[mi][1] = (base + 8 < NP) ? g_labels1[b][base + 8] : -1;
    }
    float rs[2][2] = {{0.f, 0.f}, {0.f, 0.f}};

    const uint32_t asmb = (uint32_t)__cvta_generic_to_shared(Asm);
    const uint32_t bsmb = (uint32_t)__cvta_generic_to_shared(Bsm);

    for (int nt = 0; nt < NTPC; nt++) {
        const int n0 = n_base + nt * 128;
        __syncthreads();
        const __half* Bg = &g_Bh[b][n0][0];
        #pragma unroll
        for (int i = 0; i < 8; i++) {
            int q = tid + i * 256;
            int r = q >> 4;
            int c = q & 15;
            uint4 v = *reinterpret_cast<const uint4*>(Bg + (size_t)r * 128 + c * 8);
            int sc = c ^ (r & 7);
            *reinterpret_cast<uint4*>(Bsm + r * 128 + sc * 8) = v;
        }
        if (tid < 128) nlab[tid] = g_neg_labels[b][n0 + tid];
        __syncthreads();

        float acc[2][8][4];
        #pragma unroll
        for (int mi = 0; mi < 2; mi++)
            #pragma unroll
            for (int ni = 0; ni < 8; ni++)
                #pragma unroll
                for (int x = 0; x < 4; x++) acc[mi][ni][x] = 0.0f;

        #pragma unroll
        for (int kk = 0; kk < 8; kk++) {
            const int k0 = kk * 16;
            uint32_t afr[2][4];
            #pragma unroll
            for (int mi = 0; mi < 2; mi++) {
                int row = wm * 32 + mi * 16 + (lane & 7) + 8 * ((lane >> 3) & 1);
                int k8  = k0 + 8 * (lane >> 4);
                ldmx4(afr[mi], asmb + 2 * swz(row, k8));
            }
            uint32_t bfr[8][2];
            #pragma unroll
            for (int nj = 0; nj < 4; nj++) {
                int nrow = wn * 64 + nj * 16 + (lane & 7) + 8 * (lane >> 4);
                int k8   = k0 + 8 * ((lane >> 3) & 1);
                uint32_t r4[4];
                ldmx4(r4, bsmb + 2 * swz(nrow, k8));
                bfr[nj * 2][0]     = r4[0]; bfr[nj * 2][1]     = r4[1];
                bfr[nj * 2 + 1][0] = r4[2]; bfr[nj * 2 + 1][1] = r4[3];
            }
            #pragma unroll
            for (int mi = 0; mi < 2; mi++)
                #pragma unroll
                for (int ni = 0; ni < 8; ni++)
                    mma16816(acc[mi][ni], afr[mi], bfr[ni]);
        }

        #pragma unroll
        for (int ni = 0; ni < 8; ni++) {
            int c0  = wn * 64 + ni * 8 + 2 * (lane & 3);
            int ln0 = nlab[c0];
            int ln1 = nlab[c0 + 1];
            #pragma unroll
            for (int mi = 0; mi < 2; mi++) {
                float e0 = ex2f(acc[mi][ni][0]);
                float e1 = ex2f(acc[mi][ni][1]);
                float e2 = ex2f(acc[mi][ni][2]);
                float e3 = ex2f(acc[mi][ni][3]);
                rs[mi][0] += (lp2[mi][0] != ln0 ? e0 : 0.f) + (lp2[mi][0] != ln1 ? e1 : 0.f);
                rs[mi][1] += (lp2[mi][1] != ln0 ? e2 : 0.f) + (lp2[mi][1] != ln1 ? e3 : 0.f);
            }
        }
    }

    #pragma unroll
    for (int mi = 0; mi < 2; mi++)
        #pragma unroll
        for (int h = 0; h < 2; h++) {
            float s = rs[mi][h];
            s += __shfl_xor_sync(0xffffffffu, s, 1);
            s += __shfl_xor_sync(0xffffffffu, s, 2);
            int p = p0 + wm * 32 + mi * 16 + (lane >> 2) + h * 8;
            if ((lane & 3) == 0 && p < NP)
                atomicAdd(&g_neg_logits[b][p], s);
        }
#endif
}

// ---------------------------------------------------------------------------
// Finalize (fast intrinsics; tiny kernel)
// ---------------------------------------------------------------------------
__global__ void finalize_kernel(float* __restrict__ out) {
    __shared__ float s_num[1024];
    __shared__ float s_den[1024];
    const int tid = threadIdx.x;
    float total = 0.0f;

    for (int b = 0; b < BATCH; b++) {
        float num = 0.0f, den = 0.0f;
        for (int p = tid; p < NP; p += 1024) {
            float pe  = __expf(g_pos1[b][p]);
            float neg = g_neg_logits[b][p];
            float lossn = -__logf(pe / (pe + neg + EPS) + EPS);
            float m = g_mask1[b][p];
            num += m * lossn;
            den += m;
        }
        s_num[tid] = num; s_den[tid] = den;
        __syncthreads();
        for (int s = 512; s > 0; s >>= 1) {
            if (tid < s) { s_num[tid] += s_num[tid + s]; s_den[tid] += s_den[tid + s]; }
            __syncthreads();
        }
        if (tid == 0) total += s_num[0] / (s_den[0] + EPS);
        __syncthreads();
    }
    if (tid == 0) out[0] = 0.1f * total;
}

// ---------------------------------------------------------------------------
extern "C" void kernel_launch(void* const* d_in, const int* in_sizes, int n_in,
                              void* d_out, int out_size) {
    const float* feats_view1 = (const float*)d_in[0];  // [2,128,240,240]
    const float* pos_feats1  = (const float*)d_in[1];  // [2,128,60,60]
    const float* pos_feats2  = (const float*)d_in[2];  // [2,128,60,60]
    const float* plog1       = (const float*)d_in[3];  // [2,19,60,60]
    const float* plog2       = (const float*)d_in[4];  // [2,19,60,60]
    const float* neg_plog    = (const float*)d_in[5];  // [2,19,240,240]
    float* out = (float*)d_out;

    static __half* pA = nullptr;
    static __half* pB = nullptr;
    if (!pA) { cudaGetSymbolAddress((void**)&pA, g_Ah); }
    if (!pB) { cudaGetSymbolAddress((void**)&pB, g_Bh); }

    static bool attr_set = false;
    if (!attr_set) {
        cudaFuncSetAttribute(neg_gemm_kernel,
                             cudaFuncAttributeMaxDynamicSharedMemorySize, SMEM_REQ);
        attr_set = true;
    }

    {
        dim3 grid((NP + 255) / 256, BATCH);
        prep_anchor_kernel<<<grid, 256>>>(pos_feats1, pos_feats2, plog1, plog2);
    }
    {
        dim3 grid((NN + 255) / 256, BATCH);
        prep_neg_kernel<<<grid, 256>>>(neg_plog);
    }
    {   // A: f1 [D][P] -> [P_pad][D] f16, prescaled by 10*log2(e)
        dim3 grid(NP_PAD / 32, DIMD / 32, BATCH);
        conv_transpose_kernel<<<grid, dim3(32, 8)>>>(pos_feats1, pA, NP, NP_PAD, A_SCALE);
    }
    {   // B: nf [D][N] -> [N][D] f16
        dim3 grid(NN / 32, DIMD / 32, BATCH);
        conv_transpose_kernel<<<grid, dim3(32, 8)>>>(feats_view1, pB, NN, NN, 1.0f);
    }
    {
        dim3 grid(GROUPS_N, NP_PAD / 128, BATCH);   // (25, 29, 2)
        neg_gemm_kernel<<<grid, 256, SMEM_REQ>>>();
    }
    finalize_kernel<<<1, 1024>>>(out);
}

// round 13
// speedup vs baseline: 12.7130x; 1.0339x over previous
#include <cuda_runtime.h>
#include <cuda_fp16.h>
#include <cstdint>

// Problem constants (fixed shapes from the reference)
#define BATCH 2
#define DIMD  128
#define NCLS  19
#define NP    3600    // 60*60 anchors
#define NP_PAD 3712   // 29 tiles of 128
#define NN    57600   // 240*240 negatives
#define INV_TEMP 10.0f
// A is prescaled by 10*log2(e) so the epilogue uses a single EX2 per element.
#define A_SCALE 14.4269504088896340736f
#define GAMMA 0.75f
#define EPS 1e-8f

// GEMM config: each CTA owns one 128-row A tile and streams NTPC N-tiles of 128
#define NTPC 18
#define GROUPS_N 25   // 25*18*128 = 57600

// idesc: kind::f16, dtype F32 (1<<4), a/b F16 (0), N=128 (16<<17), M=128 (8<<24)
#define MMA_IDESC 0x08200010u

// Does this device-compilation pass have the sm_103a arch-specific features?
#if defined(__CUDA_ARCH__) && \
    (defined(__CUDA_ARCH_FEAT_SM103_ALL) || \
     (defined(__CUDA_ARCH_SPECIFIC__) && (__CUDA_ARCH_SPECIFIC__ == 1030)) || \
     (defined(__CUDA_ARCH_FAMILY_SPECIFIC__) && (__CUDA_ARCH_FAMILY_SPECIFIC__ == 1030)))
#define HAVE_TC5 1
#else
#define HAVE_TC5 0
#endif

// Scratch (device globals, no allocation)
__device__ float g_neg_logits[BATCH][NP];
__device__ float g_pos1[BATCH][NP];
__device__ float g_mask1[BATCH][NP];
__device__ int   g_labels1[BATCH][NP];
__device__ int   g_neg_labels[BATCH][NN];
__device__ __half g_Ah[BATCH][NP_PAD][DIMD];  // f1^T * 10*log2(e), f16
__device__ __half g_Bh[BATCH][NN][DIMD];      // nf^T, f16

__device__ __forceinline__ float ex2f(float x) {
    float r;
    asm("ex2.approx.ftz.f32 %0, %1;" : "=f"(r) : "f"(x));
    return r;
}

// ---------------------------------------------------------------------------
// Fused prep kernel: one launch, blocks partitioned into 4 independent
// sections (B conversion dominates; the small sections fill idle SMs).
//   [0, 14400)            : conv-transpose B  (nf fp32 [D][NN] -> f16 [NN][D])
//   [14400, 15328)        : conv-transpose A  (f1 -> f16 [NP_PAD][D], *A_SCALE)
//   [15328, 15778)        : neg-label argmax
//   [15778, 15808)        : anchor prep (labels1/mask1/pos1/zero)
// ---------------------------------------------------------------------------
#define NB_CONVB 14400   // (NN/32) * (DIMD/32) * BATCH = 1800*4*2
#define NB_CONVA 928     // (NP_PAD/32) * 4 * 2 = 116*4*2
#define NB_NEG   450     // 225 per batch
#define NB_ANCH  30      // 15 per batch
#define NB_TOTAL (NB_CONVB + NB_CONVA + NB_NEG + NB_ANCH)

__device__ __forceinline__ void conv_section(const float* __restrict__ s,
                                             __half* __restrict__ d,
                                             int ncols, int nrows_pad, float scale,
                                             int bx, int by, int tid,
                                             float (*tile)[33]) {
    const int tx = tid & 31;
    const int ty = tid >> 5;
    const int px = bx * 32;   // source col == dst row
    const int dy = by * 32;   // d dimension
    #pragma unroll
    for (int i = 0; i < 4; i++) {
        int dd = dy + ty + i * 8;
        int p  = px + tx;
        float v = (p < ncols) ? s[(size_t)dd * ncols + p] : 0.0f;
        tile[ty + i * 8][tx] = v * scale;
    }
    __syncthreads();
    // write: each thread emits __half2 pairs (coalesced 128B/warp)
    #pragma unroll
    for (int i = 0; i < 2; i++) {
        int q    = tid + i * 256;      // 0..511
        int row  = q >> 4;             // p-local 0..31
        int col2 = q & 15;             // d-pair 0..15
        int p = px + row;
        if (p < nrows_pad) {
            __half2 h = __floats2half2_rn(tile[col2 * 2][row], tile[col2 * 2 + 1][row]);
            *reinterpret_cast<__half2*>(d + (size_t)p * DIMD + dy + col2 * 2) = h;
        }
    }
}

__global__ __launch_bounds__(256)
void prep_all_kernel(const float* __restrict__ feats_view1,
                     const float* __restrict__ pos_feats1,
                     const float* __restrict__ pos_feats2,
                     const float* __restrict__ pl1,
                     const float* __restrict__ pl2,
                     const float* __restrict__ npl,
                     __half* __restrict__ pA,
                     __half* __restrict__ pB) {
    __shared__ float tile[32][33];
    const int bid = blockIdx.x;
    const int tid = threadIdx.x;

    if (bid < NB_CONVB) {
        // B: nf [D][NN] -> f16 [NN][D]
        int bz  = bid / (NB_CONVB / BATCH);
        int rem = bid % (NB_CONVB / BATCH);
        int by  = rem / (NN / 32);
        int bx  = rem % (NN / 32);
        conv_section(feats_view1 + (size_t)bz * DIMD * NN,
                     pB + (size_t)bz * NN * DIMD,
                     NN, NN, 1.0f, bx, by, tid, tile);
    } else if (bid < NB_CONVB + NB_CONVA) {
        // A: f1 [D][NP] -> f16 [NP_PAD][D] * A_SCALE
        int b2  = bid - NB_CONVB;
        int bz  = b2 / (NB_CONVA / BATCH);
        int rem = b2 % (NB_CONVA / BATCH);
        int by  = rem / (NP_PAD / 32);
        int bx  = rem % (NP_PAD / 32);
        conv_section(pos_feats1 + (size_t)bz * DIMD * NP,
                     pA + (size_t)bz * NP_PAD * DIMD,
                     NP, NP_PAD, A_SCALE, bx, by, tid, tile);
    } else if (bid < NB_CONVB + NB_CONVA + NB_NEG) {
        // neg-label argmax
        int b3 = bid - NB_CONVB - NB_CONVA;
        int b  = b3 / (NB_NEG / BATCH);
        int n  = (b3 % (NB_NEG / BATCH)) * 256 + tid;
        const float* nplb = npl + (size_t)b * NCLS * NN;
        float best = -1e30f; int bi = 0;
        #pragma unroll
        for (int c = 0; c < NCLS; c++) {
            float v = nplb[c * NN + n];
            if (v > best) { best = v; bi = c; }
        }
        g_neg_labels[b][n] = bi;
    } else {
        // anchor prep
        int b4 = bid - NB_CONVB - NB_CONVA - NB_NEG;
        int b  = b4 / (NB_ANCH / BATCH);
        int p  = (b4 % (NB_ANCH / BATCH)) * 256 + tid;
        if (p >= NP) return;

        const float* pl1b = pl1 + (size_t)b * NCLS * NP;
        const float* pl2b = pl2 + (size_t)b * NCLS * NP;

        float best = -1e30f; int bi = 0;
        #pragma unroll
        for (int c = 0; c < NCLS; c++) {
            float v = pl1b[c * NP + p];
            if (v > best) { best = v; bi = c; }
        }
        g_labels1[b][p] = bi;

        int mi = -1;
        #pragma unroll
        for (int c = 0; c < NCLS; c++) {
            float a = pl1b[c * NP + p];
            float q = pl2b[c * NP + p];
            if (mi < 0 && (a < q) && (q > GAMMA)) mi = c;
        }
        g_mask1[b][p] = (mi < 0) ? 0.0f : (float)mi;

        const float* f1b = pos_feats1 + (size_t)b * DIMD * NP;
        const float* f2b = pos_feats2 + (size_t)b * DIMD * NP;
        float acc = 0.0f;
        #pragma unroll 8
        for (int d = 0; d < DIMD; d++)
            acc += f1b[d * NP + p] * f2b[d * NP + p];
        g_pos1[b][p] = acc * INV_TEMP;

        g_neg_logits[b][p] = 0.0f;
    }
}

// ---------------------------------------------------------------------------
// SMEM layout (bytes, from 1024-aligned base) -- tcgen05 path
// ---------------------------------------------------------------------------
#define OFF_A     0u
#define OFF_B     32768u
#define OFF_NLAB  98304u      // NTPC * 128 ints
#define OFF_TPTR  107520u
#define OFF_MBAR  107528u
#define SMEM_REQ  (107544 + 1024)

#if HAVE_TC5
// ---------------------------------------------------------------------------
// tcgen05 helpers (sm_103a-only pass)
// ---------------------------------------------------------------------------
static constexpr uint64_t SMEM_DESC_BASE_SW128 =
    (uint64_t(2)  << 61) | (uint64_t(1) << 46) | (uint64_t(64) << 32) | (uint64_t(1) << 16);

__device__ __forceinline__ uint64_t make_desc(uint32_t saddr) {
    return SMEM_DESC_BASE_SW128 | ((uint64_t)(saddr >> 4) & 0x3FFF);
}

__device__ __forceinline__ bool elect1() {
    uint32_t p;
    asm volatile("{\n\t.reg .pred p;\n\telect.sync _|p, 0xFFFFFFFF;\n\tselp.b32 %0, 1, 0, p;\n\t}"
                 : "=r"(p));
    return p != 0;
}

__device__ __forceinline__ void mma_f16_ss(uint32_t d, uint64_t a, uint64_t b,
                                           uint32_t en) {
    asm volatile(
        "{\n\t.reg .pred p;\n\tsetp.ne.u32 p, %4, 0;\n\t"
        "tcgen05.mma.cta_group::1.kind::f16 [%0], %1, %2, %3, {%5,%5,%5,%5}, p;\n\t}"
        :: "r"(d), "l"(a), "l"(b), "r"(MMA_IDESC), "r"(en), "r"(0u)
        : "memory");
}

__device__ __forceinline__ void mbar_init(uint32_t a, uint32_t cnt) {
    asm volatile("mbarrier.init.shared.b64 [%0], %1;" :: "r"(a), "r"(cnt) : "memory");
}
__device__ __forceinline__ void mbar_wait(uint32_t a, uint32_t ph) {
    asm volatile(
        "{\n\t.reg .pred P1;\n\t"
        "W0_%=:\n\t"
        "mbarrier.try_wait.parity.acquire.cta.shared::cta.b64 P1, [%0], %1, 0x989680;\n\t"
        "@P1 bra W1_%=;\n\t"
        "bra W0_%=;\n\t"
        "W1_%=:\n\t}"
        :: "r"(a), "r"(ph) : "memory");
}

#define TC_ALLOC(sa, n)  asm volatile("tcgen05.alloc.cta_group::1.sync.aligned.shared::cta.b32 [%0], %1;" :: "r"(sa), "r"(n) : "memory")
#define TC_RELINQ()      asm volatile("tcgen05.relinquish_alloc_permit.cta_group::1.sync.aligned;")
#define TC_DEALLOC(t, n) asm volatile("tcgen05.dealloc.cta_group::1.sync.aligned.b32 %0, %1;" :: "r"(t), "r"(n))
#define TC_COMMIT(mb)    asm volatile("tcgen05.commit.cta_group::1.mbarrier::arrive::one.shared::cluster.b64 [%0];" :: "r"(mb) : "memory")
#define TC_WAIT_LD()     asm volatile("tcgen05.wait::ld.sync.aligned;" ::: "memory")
#define TC_FENCE_AFTER() asm volatile("tcgen05.fence::after_thread_sync;" ::: "memory")
#define TC_FENCE_BEFORE() asm volatile("tcgen05.fence::before_thread_sync;" ::: "memory")
#define PROXY_FENCE()    asm volatile("fence.proxy.async.shared::cta;" ::: "memory")
#define CP_COMMIT()      asm volatile("cp.async.commit_group;" ::: "memory")
#define CP_WAIT0()       asm volatile("cp.async.wait_group 0;" ::: "memory")
#define CP_WAIT1()       asm volatile("cp.async.wait_group 1;" ::: "memory")

#define LDTM_X32(r, a) \
    asm volatile("tcgen05.ld.sync.aligned.32x32b.x32.b32 " \
        "{%0, %1, %2, %3, %4, %5, %6, %7, " \
        " %8, %9, %10, %11, %12, %13, %14, %15, " \
        " %16, %17, %18, %19, %20, %21, %22, %23, " \
        " %24, %25, %26, %27, %28, %29, %30, %31}, [%32];" \
        : "=r"((r)[0]),  "=r"((r)[1]),  "=r"((r)[2]),  "=r"((r)[3]), \
          "=r"((r)[4]),  "=r"((r)[5]),  "=r"((r)[6]),  "=r"((r)[7]), \
          "=r"((r)[8]),  "=r"((r)[9]),  "=r"((r)[10]), "=r"((r)[11]), \
          "=r"((r)[12]), "=r"((r)[13]), "=r"((r)[14]), "=r"((r)[15]), \
          "=r"((r)[16]), "=r"((r)[17]), "=r"((r)[18]), "=r"((r)[19]), \
          "=r"((r)[20]), "=r"((r)[21]), "=r"((r)[22]), "=r"((r)[23]), \
          "=r"((r)[24]), "=r"((r)[25]), "=r"((r)[26]), "=r"((r)[27]), \
          "=r"((r)[28]), "=r"((r)[29]), "=r"((r)[30]), "=r"((r)[31]) \
        : "r"(a))

// cp.async a [128 rows x 128 f16] row-major global tile into K-blocked
// SW128 SMEM: two blocks of [128 rows x 64 f16] (128B rows, XOR swizzle).
__device__ __forceinline__ void cp_tile128(const __half* __restrict__ g,
                                           uint32_t s_base, int tid) {
    #pragma unroll
    for (int i = 0; i < 8; i++) {
        int q = tid + i * 256;         // 16B-chunk index, 2048 total
        int r = q >> 4;                // row 0..127
        int c = q & 15;                // chunk 0..15
        int blk = c >> 3;
        int cc  = (c & 7) ^ (r & 7);
        uint32_t sa = s_base + blk * 16384u + (uint32_t)r * 128u + (uint32_t)cc * 16u;
        const void* ga = (const void*)(g + (size_t)r * 128 + c * 8);
        asm volatile("cp.async.cg.shared.global [%0], [%1], 16;"
                     :: "r"(sa), "l"(ga) : "memory");
    }
}

// exp2 of two fp32 values via one MUFU op (f16x2): inputs are log2-domain
// scores (|x| small); independent per-element rounding -> error ~1e-5 on sums.
__device__ __forceinline__ float2 ex2_pair(float lo, float hi) {
    uint32_t h;
    asm("cvt.rn.f16x2.f32 %0, %1, %2;" : "=r"(h) : "f"(hi), "f"(lo));
    asm("ex2.approx.f16x2 %0, %0;" : "+r"(h));
    return __half22float2(*reinterpret_cast<__half2*>(&h));
}
#endif  // HAVE_TC5

#if !HAVE_TC5
// ---------------------------------------------------------------------------
// Fallback helpers: mma.sync m16n8k16 f16 (compiles on any >= sm_80 target)
// ---------------------------------------------------------------------------
__device__ __forceinline__ void ldmx4(uint32_t* r, uint32_t saddr) {
    asm volatile("ldmatrix.sync.aligned.m8n8.x4.shared.b16 {%0,%1,%2,%3}, [%4];"
                 : "=r"(r[0]), "=r"(r[1]), "=r"(r[2]), "=r"(r[3]) : "r"(saddr));
}
__device__ __forceinline__ void mma16816(float* c, const uint32_t* a, const uint32_t* b) {
    asm volatile("mma.sync.aligned.m16n8k16.row.col.f32.f16.f16.f32 "
                 "{%0,%1,%2,%3}, {%4,%5,%6,%7}, {%8,%9}, {%0,%1,%2,%3};"
                 : "+f"(c[0]), "+f"(c[1]), "+f"(c[2]), "+f"(c[3])
                 : "r"(a[0]), "r"(a[1]), "r"(a[2]), "r"(a[3]), "r"(b[0]), "r"(b[1]));
}
// swizzled element offset in a flat [r][128] f16 tile (16B-chunk XOR swizzle)
__device__ __forceinline__ int swz(int r, int k) {
    return r * 128 + ((((k) >> 3) ^ (r & 7)) << 3) + (k & 7);
}
#endif  // !HAVE_TC5

// ---------------------------------------------------------------------------
// GEMM + fused masked-exp row-sum epilogue. One kernel name, two bodies:
// tcgen05 (sm_103a cubin) or mma.sync (virtual-arch / JIT fallback).
// Grid: (GROUPS_N, NP_PAD/128, BATCH), 256 threads, SMEM_REQ dynamic smem.
// ---------------------------------------------------------------------------
__global__ __launch_bounds__(256, 2)
void neg_gemm_kernel() {
    extern __shared__ __align__(16) uint8_t dynsmem[];
    uint8_t* smem = (uint8_t*)(((uintptr_t)dynsmem + 1023) & ~(uintptr_t)1023);

    const int b      = blockIdx.z;
    const int p0     = blockIdx.y * 128;
    const int n_base = blockIdx.x * (NTPC * 128);
    const int tid    = threadIdx.x;
    const int wid    = tid >> 5;
    const int lane   = tid & 31;

#if HAVE_TC5
    // ======================= tcgen05 pipelined path =======================
    const uint32_t sb    = (uint32_t)__cvta_generic_to_shared(smem);
    const uint32_t mbar0 = sb + OFF_MBAR;
    const uint32_t mbar1 = sb + OFF_MBAR + 8;
    int* nlabAll = (int*)(smem + OFF_NLAB);

    if (wid == 0) {
        TC_ALLOC(sb + OFF_TPTR, 256u);
        TC_RELINQ();
    }
    if (tid == 0) { mbar_init(mbar0, 1); mbar_init(mbar1, 1); }

    // prologue: async-load A + B0 (group 0), B1 (group 1); labels for all tiles
    cp_tile128(&g_Ah[b][p0][0], sb + OFF_A, tid);
    cp_tile128(&g_Bh[b][n_base][0], sb + OFF_B, tid);
    CP_COMMIT();
    cp_tile128(&g_Bh[b][n_base + 128][0], sb + OFF_B + 32768u, tid);
    CP_COMMIT();
    #pragma unroll
    for (int i = 0; i < NTPC * 128 / 256; i++)
        nlabAll[tid + i * 256] = g_neg_labels[b][n_base + tid + i * 256];

    CP_WAIT1();        // A + B0 resident
    PROXY_FENCE();
    __syncthreads();

    const uint32_t tmem_base = *reinterpret_cast<uint32_t*>(smem + OFF_TPTR);
    const uint64_t adesc = make_desc(sb + OFF_A);

    // issue MMA for tile 0
    if (wid == 0) {
        TC_FENCE_AFTER();
        if (elect1()) {
            uint64_t bdesc = make_desc(sb + OFF_B);
            #pragma unroll
            for (int kk = 0; kk < 8; kk++) {
                uint64_t koff = (uint64_t)((kk >> 2) * 1024 + (kk & 3) * 2);
                mma_f16_ss(tmem_base, adesc + koff, bdesc + koff, kk > 0);
            }
            TC_COMMIT(mbar0);
        }
    }

    const int myrow = (wid & 3) * 32 + lane;
    const int myp   = p0 + myrow;
    const int lp    = (myp < NP) ? g_labels1[b][myp] : -1;
    float rs0 = 0.0f, rs1 = 0.0f;
    const int cbase = (wid >> 2) * 64;  // warpgroup n-column split

    for (int nt = 1; nt <= NTPC; nt++) {
        const int prev = nt - 1;

        // MMA prev done (issued one epilogue ago -> fast-path wait)
        mbar_wait((prev & 1) ? mbar1 : mbar0, (prev >> 1) & 1);

        if (nt < NTPC) {
            // prefetch B[nt+1] into the buffer MMA prev just released
            if (nt + 1 < NTPC) {
                cp_tile128(&g_Bh[b][n_base + (nt + 1) * 128][0],
                           sb + OFF_B + (uint32_t)((nt + 1) & 1) * 32768u, tid);
                CP_COMMIT();
                CP_WAIT1();      // B[nt] resident
            } else {
                CP_WAIT0();      // B[nt] resident, no more prefetch
            }
            PROXY_FENCE();
        }
        __syncthreads();

        if (nt < NTPC && wid == 0) {
            TC_FENCE_AFTER();
            if (elect1()) {
                uint64_t bdesc = make_desc(sb + OFF_B + (uint32_t)(nt & 1) * 32768u);
                uint32_t dtm = tmem_base + (nt & 1) * 128;
                #pragma unroll
                for (int kk = 0; kk < 8; kk++) {
                    uint64_t koff = (uint64_t)((kk >> 2) * 1024 + (kk & 3) * 2);
                    mma_f16_ss(dtm, adesc + koff, bdesc + koff, kk > 0);
                }
                TC_COMMIT((nt & 1) ? mbar1 : mbar0);
            }
        }

        // ---- epilogue tile prev (overlaps MMA nt + prefetch B nt+1) ----
        // Pipelined LDTMs; exp2 two-at-a-time via one MUFU f16x2 op.
        TC_FENCE_AFTER();
        const int* nl = nlabAll + prev * 128;
        const uint32_t dtm_prev = tmem_base + (prev & 1) * 128;
        uint32_t r0[32], r1[32];
        LDTM_X32(r0, dtm_prev + cbase);
        TC_WAIT_LD();
        LDTM_X32(r1, dtm_prev + cbase + 32);
        #pragma unroll
        for (int j = 0; j < 32; j += 2) {
            float2 e = ex2_pair(__uint_as_float(r0[j]), __uint_as_float(r0[j + 1]));
            rs0 += (lp != nl[cbase + j])     ? e.x : 0.0f;
            rs1 += (lp != nl[cbase + j + 1]) ? e.y : 0.0f;
        }
        TC_WAIT_LD();
        #pragma unroll
        for (int j = 0; j < 32; j += 2) {
            float2 e = ex2_pair(__uint_as_float(r1[j]), __uint_as_float(r1[j + 1]));
            rs0 += (lp != nl[cbase + 32 + j])     ? e.x : 0.0f;
            rs1 += (lp != nl[cbase + 32 + j + 1]) ? e.y : 0.0f;
        }
        TC_FENCE_BEFORE();
    }

    if (myp < NP)
        atomicAdd(&g_neg_logits[b][myp], rs0 + rs1);

    __syncthreads();
    if (wid == 0) TC_DEALLOC(tmem_base, 256u);

#else
    // ======================= mma.sync fallback path =======================
    __half* Asm = (__half*)smem;             // 32KB (flat [128][128] swz)
    __half* Bsm = (__half*)(smem + 32768u);  // 32KB
    int* nlab = (int*)(smem + 65536u);       // 128 ints

    const int wm = wid & 3;    // m sub-block (32 rows)
    const int wn = wid >> 2;   // n sub-block (64 cols)

    const __half* Ag = &g_Ah[b][p0][0];
    #pragma unroll
    for (int i = 0; i < 8; i++) {
        int q = tid + i * 256;
        int r = q >> 4;
        int c = q & 15;
        uint4 v = *reinterpret_cast<const uint4*>(Ag + (size_t)r * 128 + c * 8);
        int sc = c ^ (r & 7);
        *reinterpret_cast<uint4*>(Asm + r * 128 + sc * 8) = v;
    }

    int lp2[2][2];
    #pragma unroll
    for (int mi = 0; mi < 2; mi++) {
        int base = p0 + wm * 32 + mi * 16 + (lane >> 2);
        lp2[mi][0] = (base     < NP) ? g_labels1[b][base]     : -1;
        lp2[mi][1] = (base + 8 < NP) ? g_labels1[b][base + 8] : -1;
    }
    float rs[2][2] = {{0.f, 0.f}, {0.f, 0.f}};

    const uint32_t asmb = (uint32_t)__cvta_generic_to_shared(Asm);
    const uint32_t bsmb = (uint32_t)__cvta_generic_to_shared(Bsm);

    for (int nt = 0; nt < NTPC; nt++) {
        const int n0 = n_base + nt * 128;
        __syncthreads();
        const __half* Bg = &g_Bh[b][n0][0];
        #pragma unroll
        for (int i = 0; i < 8; i++) {
            int q = tid + i * 256;
            int r = q >> 4;
            int c = q & 15;
            uint4 v = *reinterpret_cast<const uint4*>(Bg + (size_t)r * 128 + c * 8);
            int sc = c ^ (r & 7);
            *reinterpret_cast<uint4*>(Bsm + r * 128 + sc * 8) = v;
        }
        if (tid < 128) nlab[tid] = g_neg_labels[b][n0 + tid];
        __syncthreads();

        float acc[2][8][4];
        #pragma unroll
        for (int mi = 0; mi < 2; mi++)
            #pragma unroll
            for (int ni = 0; ni < 8; ni++)
                #pragma unroll
                for (int x = 0; x < 4; x++) acc[mi][ni][x] = 0.0f;

        #pragma unroll
        for (int kk = 0; kk < 8; kk++) {
            const int k0 = kk * 16;
            uint32_t afr[2][4];
            #pragma unroll
            for (int mi = 0; mi < 2; mi++) {
                int row = wm * 32 + mi * 16 + (lane & 7) + 8 * ((lane >> 3) & 1);
                int k8  = k0 + 8 * (lane >> 4);
                ldmx4(afr[mi], asmb + 2 * swz(row, k8));
            }
            uint32_t bfr[8][2];
            #pragma unroll
            for (int nj = 0; nj < 4; nj++) {
                int nrow = wn * 64 + nj * 16 + (lane & 7) + 8 * (lane >> 4);
                int k8   = k0 + 8 * ((lane >> 3) & 1);
                uint32_t r4[4];
                ldmx4(r4, bsmb + 2 * swz(nrow, k8));
                bfr[nj * 2][0]     = r4[0]; bfr[nj * 2][1]     = r4[1];
                bfr[nj * 2 + 1][0] = r4[2]; bfr[nj * 2 + 1][1] = r4[3];
            }
            #pragma unroll
            for (int mi = 0; mi < 2; mi++)
                #pragma unroll
                for (int ni = 0; ni < 8; ni++)
                    mma16816(acc[mi][ni], afr[mi], bfr[ni]);
        }

        #pragma unroll
        for (int ni = 0; ni < 8; ni++) {
            int c0  = wn * 64 + ni * 8 + 2 * (lane & 3);
            int ln0 = nlab[c0];
            int ln1 = nlab[c0 + 1];
            #pragma unroll
            for (int mi = 0; mi < 2; mi++) {
                float e0 = ex2f(acc[mi][ni][0]);
                float e1 = ex2f(acc[mi][ni][1]);
                float e2 = ex2f(acc[mi][ni][2]);
                float e3 = ex2f(acc[mi][ni][3]);
                rs[mi][0] += (lp2[mi][0] != ln0 ? e0 : 0.f) + (lp2[mi][0] != ln1 ? e1 : 0.f);
                rs[mi][1] += (lp2[mi][1] != ln0 ? e2 : 0.f) + (lp2[mi][1] != ln1 ? e3 : 0.f);
            }
        }
    }

    #pragma unroll
    for (int mi = 0; mi < 2; mi++)
        #pragma unroll
        for (int h = 0; h < 2; h++) {
            float s = rs[mi][h];
            s += __shfl_xor_sync(0xffffffffu, s, 1);
            s += __shfl_xor_sync(0xffffffffu, s, 2);
            int p = p0 + wm * 32 + mi * 16 + (lane >> 2) + h * 8;
            if ((lane & 3) == 0 && p < NP)
                atomicAdd(&g_neg_logits[b][p], s);
        }
#endif
}

// ---------------------------------------------------------------------------
// Finalize (fast intrinsics; tiny kernel)
// ---------------------------------------------------------------------------
__global__ void finalize_kernel(float* __restrict__ out) {
    __shared__ float s_num[1024];
    __shared__ float s_den[1024];
    const int tid = threadIdx.x;
    float total = 0.0f;

    for (int b = 0; b < BATCH; b++) {
        float num = 0.0f, den = 0.0f;
        for (int p = tid; p < NP; p += 1024) {
            float pe  = __expf(g_pos1[b][p]);
            float neg = g_neg_logits[b][p];
            float lossn = -__logf(pe / (pe + neg + EPS) + EPS);
            float m = g_mask1[b][p];
            num += m * lossn;
            den += m;
        }
        s_num[tid] = num; s_den[tid] = den;
        __syncthreads();
        for (int s = 512; s > 0; s >>= 1) {
            if (tid < s) { s_num[tid] += s_num[tid + s]; s_den[tid] += s_den[tid + s]; }
            __syncthreads();
        }
        if (tid == 0) total += s_num[0] / (s_den[0] + EPS);
        __syncthreads();
    }
    if (tid == 0) out[0] = 0.1f * total;
}

// ---------------------------------------------------------------------------
extern "C" void kernel_launch(void* const* d_in, const int* in_sizes, int n_in,
                              void* d_out, int out_size) {
    const float* feats_view1 = (const float*)d_in[0];  // [2,128,240,240]
    const float* pos_feats1  = (const float*)d_in[1];  // [2,128,60,60]
    const float* pos_feats2  = (const float*)d_in[2];  // [2,128,60,60]
    const float* plog1       = (const float*)d_in[3];  // [2,19,60,60]
    const float* plog2       = (const float*)d_in[4];  // [2,19,60,60]
    const float* neg_plog    = (const float*)d_in[5];  // [2,19,240,240]
    float* out = (float*)d_out;

    static __half* pA = nullptr;
    static __half* pB = nullptr;
    if (!pA) { cudaGetSymbolAddress((void**)&pA, g_Ah); }
    if (!pB) { cudaGetSymbolAddress((void**)&pB, g_Bh); }

    static bool attr_set = false;
    if (!attr_set) {
        cudaFuncSetAttribute(neg_gemm_kernel,
                             cudaFuncAttributeMaxDynamicSharedMemorySize, SMEM_REQ);
        attr_set = true;
    }

    prep_all_kernel<<<NB_TOTAL, 256>>>(feats_view1, pos_feats1, pos_feats2,
                                       plog1, plog2, neg_plog, pA, pB);
    {
        dim3 grid(GROUPS_N, NP_PAD / 128, BATCH);   // (25, 29, 2)
        neg_gemm_kernel<<<grid, 256, SMEM_REQ>>>();
    }
    finalize_kernel<<<1, 1024>>>(out);
}